// round 14
// baseline (speedup 1.0000x reference)
#include <cuda_runtime.h>
#include <math.h>

#define NPREDN 100000
#define NTOTN  120000
#define NUIN   200000
#define NNODESN 220000
#define EMBD 64
#define MAXE 1500000
#define RPSZ 200001
#define XSTRIDE 66   // transposed X tile row stride (floats): even -> 8B aligned pairs

typedef unsigned long long ull;

// ---------------- device scratch (static, no allocations) ----------------
__device__ float g_ebn[NNODESN*EMBD];
__device__ float g_uie[NUIN*EMBD];
__device__ float g_fs[NUIN*EMBD];
__device__ float g_fd[NUIN*EMBD];
__device__ float g_gout[NUIN*EMBD];
__device__ float g_u2i[NUIN*EMBD];
__device__ float g_rc[NUIN*EMBD];
__device__ float g_T1[NTOTN*EMBD];
__device__ float g_T2[NTOTN*EMBD];
__device__ float g_ch[NTOTN*EMBD];
__device__ float g_ch2[NTOTN*EMBD];
__device__ float g_i2u[NPREDN*EMBD];
__device__ float g_soc[NPREDN*EMBD];
__device__ float g_sie[NPREDN*EMBD];
__device__ float g_uitem[NPREDN*EMBD];
__device__ float g_huP[NPREDN*EMBD];
__device__ float g_huS[NPREDN*EMBD];
__device__ float g_mA[NPREDN*EMBD];
__device__ float g_mA2[NPREDN*EMBD];
__device__ float g_z[NPREDN*EMBD];
__device__ float g_stat[6*128];
// CSR sort scratch
__device__ int   g_srcs[7000000];
__device__ int   g_rowptr[5*RPSZ];
__device__ int   g_cnt[RPSZ];
__device__ int   g_pos[RPSZ];
__device__ int   g_part[256];
__device__ float g_deginv[NTOTN];
__device__ float g_normv[MAXE];

static inline int ceil_div(int a, int b) { return (a + b - 1) / b; }

__device__ __forceinline__ float lrelu(float v, float s) { return v > 0.f ? v : s*v; }

__device__ __forceinline__ ull dup_f(float x) {
    ull r; asm("mov.b64 %0, {%1,%1};" : "=l"(r) : "f"(x)); return r;
}
__device__ __forceinline__ float2 unpk(ull v) {
    float2 r; asm("mov.b64 {%0,%1}, %2;" : "=f"(r.x), "=f"(r.y) : "l"(v)); return r;
}
__device__ __forceinline__ void ffma2(ull& acc, ull a, ull b) {
    asm("fma.rn.f32x2 %0, %1, %2, %0;" : "+l"(acc) : "l"(a), "l"(b));
}

// ====== GEMM family: 64-row blocks, 128 threads, 8 rows x 4 cols per thread =======
__device__ __forceinline__ void load_x64_t(const float* __restrict__ X,
                                           const int* __restrict__ ids,
                                           float* Xt, int row0, int n, int tid)
{
    #pragma unroll
    for (int i = 0; i < 8; i++) {
        int idx = tid + i*128;
        int r = idx >> 4, c4 = idx & 15;
        int gr = row0 + r;
        float4 v = make_float4(0.f,0.f,0.f,0.f);
        if (gr < n) {
            int sr = ids ? ids[gr] : gr;
            v = ((const float4*)X)[(size_t)sr*16 + c4];
        }
        int k0 = c4*4;
        Xt[(k0+0)*XSTRIDE + r] = v.x;
        Xt[(k0+1)*XSTRIDE + r] = v.y;
        Xt[(k0+2)*XSTRIDE + r] = v.z;
        Xt[(k0+3)*XSTRIDE + r] = v.w;
    }
}
__device__ __forceinline__ void load_w64(const float* __restrict__ W, float* Ws, int tid)
{
    #pragma unroll
    for (int i = 0; i < 8; i++)
        ((float4*)Ws)[tid + i*128] = ((const float4*)W)[tid + i*128];
}

__device__ __forceinline__ void mm_f2t(const float* Xt, const float* Ws,
                                       ull acc[4][4], int tx, int ty)
{
    #pragma unroll 8
    for (int k = 0; k < 64; k++) {
        float4 b = *(const float4*)&Ws[k*64 + tx*4];
        ull b0 = dup_f(b.x), b1 = dup_f(b.y), b2 = dup_f(b.z), b3 = dup_f(b.w);
        const ull* ap = (const ull*)&Xt[k*XSTRIDE + ty*8];
        #pragma unroll
        for (int i = 0; i < 4; i++) {
            ull a = ap[i];
            ffma2(acc[i][0], a, b0);
            ffma2(acc[i][1], a, b1);
            ffma2(acc[i][2], a, b2);
            ffma2(acc[i][3], a, b3);
        }
    }
}

__device__ __forceinline__ void unpack_acc(ull acc[4][4], float f[8][4])
{
    #pragma unroll
    for (int i = 0; i < 4; i++) {
        #pragma unroll
        for (int j = 0; j < 4; j++) {
            float2 p = unpk(acc[i][j]);
            f[2*i][j]   = p.x;
            f[2*i+1][j] = p.y;
        }
    }
}

__device__ __forceinline__ void store8x4(float* __restrict__ Y, float f[8][4],
                                         const float* __restrict__ bias,
                                         int row0, int n, int tx, int ty, int act)
{
    float4 bb = bias ? ((const float4*)bias)[tx] : make_float4(0.f,0.f,0.f,0.f);
    #pragma unroll
    for (int i = 0; i < 8; i++) {
        int gr = row0 + ty*8 + i;
        if (gr < n) {
            float4 v = make_float4(f[i][0]+bb.x, f[i][1]+bb.y, f[i][2]+bb.z, f[i][3]+bb.w);
            if (act) { v.x=lrelu(v.x,0.01f); v.y=lrelu(v.y,0.01f);
                       v.z=lrelu(v.z,0.01f); v.w=lrelu(v.w,0.01f); }
            ((float4*)Y)[(size_t)gr*16 + tx] = v;
        }
    }
}

__device__ __forceinline__ void stats_epilogue(float f[8][4], float* sh,
                                               const float* __restrict__ bias,
                                               float* __restrict__ stat,
                                               int row0, int n, int tx, int ty, int tid)
{
    float4 bb = bias ? ((const float4*)bias)[tx] : make_float4(0.f,0.f,0.f,0.f);
    float s[4] = {0,0,0,0}, q[4] = {0,0,0,0};
    #pragma unroll
    for (int i = 0; i < 8; i++) {
        int gr = row0 + ty*8 + i;
        if (gr < n) {
            float v0 = f[i][0]+bb.x, v1 = f[i][1]+bb.y;
            float v2 = f[i][2]+bb.z, v3 = f[i][3]+bb.w;
            s[0]+=v0; s[1]+=v1; s[2]+=v2; s[3]+=v3;
            q[0]+=v0*v0; q[1]+=v1*v1; q[2]+=v2*v2; q[3]+=v3*v3;
        }
    }
    __syncthreads();
    #pragma unroll
    for (int k = 0; k < 4; k++) {
        sh[ty*128 + tx*8 + k]     = s[k];
        sh[ty*128 + tx*8 + 4 + k] = q[k];
    }
    __syncthreads();
    if (tid < 128) {
        float t = 0.f;
        #pragma unroll
        for (int w = 0; w < 8; w++) t += sh[w*128 + tid];
        int txx = tid >> 3, qq = tid & 7;
        int col = txx*4 + (qq & 3);
        atomicAdd(&stat[(qq < 4 ? col : 64 + col)], t);
    }
}

__global__ void __launch_bounds__(128) k_gemm_dual(
    const float* __restrict__ X, const int* __restrict__ ids,
    const float* __restrict__ W1, const float* __restrict__ b1, float* __restrict__ Y1,
    const float* __restrict__ W2, const float* __restrict__ b2, float* __restrict__ Y2,
    int n)
{
    __shared__ float Xt[64*XSTRIDE];
    __shared__ float Ws[4096];
    int tid = threadIdx.x, tx = tid & 15, ty = tid >> 4;
    int row0 = blockIdx.x * 64;
    load_x64_t(X, ids, Xt, row0, n, tid);
    load_w64(W1, Ws, tid);
    __syncthreads();
    {
        ull acc[4][4] = {};
        mm_f2t(Xt, Ws, acc, tx, ty);
        float f[8][4]; unpack_acc(acc, f);
        store8x4(Y1, f, b1, row0, n, tx, ty, 0);
    }
    __syncthreads();
    load_w64(W2, Ws, tid);
    __syncthreads();
    {
        ull acc[4][4] = {};
        mm_f2t(Xt, Ws, acc, tx, ty);
        float f[8][4]; unpack_acc(acc, f);
        store8x4(Y2, f, b2, row0, n, tx, ty, 0);
    }
}

__global__ void __launch_bounds__(128) k_gemm_cat(
    const float* __restrict__ A, const float* __restrict__ Bx,
    const float* __restrict__ W, const float* __restrict__ bias,
    float* __restrict__ Y, int n, float* __restrict__ stat)
{
    __shared__ float Xt[64*XSTRIDE];
    __shared__ float Ws[4096];
    int tid = threadIdx.x, tx = tid & 15, ty = tid >> 4;
    int row0 = blockIdx.x * 64;
    ull acc[4][4] = {};
    load_x64_t(A, nullptr, Xt, row0, n, tid);
    load_w64(W, Ws, tid);
    __syncthreads();
    mm_f2t(Xt, Ws, acc, tx, ty);
    __syncthreads();
    load_x64_t(Bx, nullptr, Xt, row0, n, tid);
    load_w64(W + 4096, Ws, tid);
    __syncthreads();
    mm_f2t(Xt, Ws, acc, tx, ty);
    float f[8][4]; unpack_acc(acc, f);
    store8x4(Y, f, bias, row0, n, tx, ty, 0);
    if (stat) stats_epilogue(f, Ws, bias, stat, row0, n, tx, ty, tid);
}

// cheb: Y = lrelu(X0@W0 + X1@W1 + X2c@W2 + bias); X2c pre-combined (2*lhat(T1)-T0)
__global__ void __launch_bounds__(128) k_gemm_cat3(
    const float* __restrict__ X0, const float* __restrict__ X1, const float* __restrict__ X2c,
    const float* __restrict__ W, const float* __restrict__ bias,
    float* __restrict__ Y, int n)
{
    __shared__ float Xt[64*XSTRIDE];
    __shared__ float Ws[4096];
    int tid = threadIdx.x, tx = tid & 15, ty = tid >> 4;
    int row0 = blockIdx.x * 64;
    ull acc[4][4] = {};
    load_x64_t(X0, nullptr, Xt, row0, n, tid);
    load_w64(W, Ws, tid);
    __syncthreads();
    mm_f2t(Xt, Ws, acc, tx, ty);
    __syncthreads();
    load_x64_t(X1, nullptr, Xt, row0, n, tid);
    load_w64(W + 4096, Ws, tid);
    __syncthreads();
    mm_f2t(Xt, Ws, acc, tx, ty);
    __syncthreads();
    load_x64_t(X2c, nullptr, Xt, row0, n, tid);
    load_w64(W + 8192, Ws, tid);
    __syncthreads();
    mm_f2t(Xt, Ws, acc, tx, ty);
    float f[8][4]; unpack_acc(acc, f);
    store8x4(Y, f, bias, row0, n, tx, ty, 1);
}

// ---------------- BN ----------------
__global__ void k_colstats(const float* __restrict__ X, int n, float* __restrict__ stat)
{
    int c  = threadIdx.x & 63;
    int tg = threadIdx.x >> 6;
    float s = 0.f, sq = 0.f;
    for (int r = blockIdx.x*4 + tg; r < n; r += gridDim.x*4) {
        float v = X[(size_t)r*64 + c];
        s += v; sq += v*v;
    }
    __shared__ float sh[4][128];
    sh[tg][c] = s; sh[tg][64+c] = sq;
    __syncthreads();
    if (tg == 0) {
        float ts = sh[0][c]+sh[1][c]+sh[2][c]+sh[3][c];
        float tq = sh[0][64+c]+sh[1][64+c]+sh[2][64+c]+sh[3][64+c];
        atomicAdd(&stat[c], ts);
        atomicAdd(&stat[64+c], tq);
    }
}

__device__ __forceinline__ float4 bn4(float4 x, float4 s1, float4 s2,
                                      float4 gg, float4 bb, float invn)
{
    float4 o;
    float mu = s1.x*invn, var = s2.x*invn - mu*mu;
    o.x = (x.x-mu)*rsqrtf(var+1e-5f)*gg.x + bb.x;
    mu = s1.y*invn; var = s2.y*invn - mu*mu;
    o.y = (x.y-mu)*rsqrtf(var+1e-5f)*gg.y + bb.y;
    mu = s1.z*invn; var = s2.z*invn - mu*mu;
    o.z = (x.z-mu)*rsqrtf(var+1e-5f)*gg.z + bb.z;
    mu = s1.w*invn; var = s2.w*invn - mu*mu;
    o.w = (x.w-mu)*rsqrtf(var+1e-5f)*gg.w + bb.w;
    return o;
}

__global__ void k_bnapply(const float* __restrict__ X, const float* __restrict__ stat,
                          const float* __restrict__ g, const float* __restrict__ b,
                          float* __restrict__ Y, int nq, float invn, int act)
{
    int i = blockIdx.x*blockDim.x + threadIdx.x;
    if (i >= nq) return;
    int c4 = i & 15;
    float4 o = bn4(((const float4*)X)[i], ((const float4*)stat)[c4],
                   ((const float4*)stat)[16+c4], ((const float4*)g)[c4],
                   ((const float4*)b)[c4], invn);
    if (act) { o.x=lrelu(o.x,0.01f); o.y=lrelu(o.y,0.01f);
               o.z=lrelu(o.z,0.01f); o.w=lrelu(o.w,0.01f); }
    ((float4*)Y)[i] = o;
}

__global__ void k_bnapply_uie(const float* __restrict__ X, const float* __restrict__ stat,
                              const float* __restrict__ g, const float* __restrict__ b,
                              float* __restrict__ ebn, float* __restrict__ uie, float invn)
{
    int i = blockIdx.x*blockDim.x + threadIdx.x;
    if (i >= NNODESN*16) return;
    int c4 = i & 15;
    float4 o = bn4(((const float4*)X)[i], ((const float4*)stat)[c4],
                   ((const float4*)stat)[16+c4], ((const float4*)g)[c4],
                   ((const float4*)b)[c4], invn);
    ((float4*)ebn)[i] = o;
    int row = i >> 4;
    if (row < NPREDN) ((float4*)uie)[i] = o;
    else if (row >= NNODESN - 100000)
        ((float4*)uie)[(size_t)(row - (NNODESN - NUIN))*16 + c4] = o;
}

// ================= counting sort by dst (CSR build) =================
__global__ void k_hist(const int* __restrict__ dst, int ne, int* __restrict__ cnt)
{
    int i = blockIdx.x*blockDim.x + threadIdx.x;
    if (i < ne) atomicAdd(&cnt[dst[i]], 1);
}
__global__ void k_scan_part(const int* __restrict__ cnt, int n, int* __restrict__ part)
{
    __shared__ int sh[256];
    int t = threadIdx.x, base = blockIdx.x*1024 + t*4;
    int s = 0;
    #pragma unroll
    for (int j = 0; j < 4; j++) { int i = base+j; if (i < n) s += cnt[i]; }
    sh[t] = s; __syncthreads();
    #pragma unroll
    for (int off = 128; off; off >>= 1) {
        if (t < off) sh[t] += sh[t+off];
        __syncthreads();
    }
    if (!t) part[blockIdx.x] = sh[0];
}
__global__ void k_scan_top(int* __restrict__ part, int nb, int* __restrict__ totptr)
{
    __shared__ int sh[256];
    int t = threadIdx.x;
    int v = t < nb ? part[t] : 0;
    sh[t] = v; __syncthreads();
    for (int off = 1; off < 256; off <<= 1) {
        int u = t >= off ? sh[t-off] : 0;
        __syncthreads();
        sh[t] += u;
        __syncthreads();
    }
    int excl = t ? sh[t-1] : 0;
    if (t < nb) part[t] = excl;
    if (t == 255) *totptr = sh[255];
}
__global__ void k_scan_final(const int* __restrict__ cnt, const int* __restrict__ part, int n,
                             int* __restrict__ rowptr, int* __restrict__ pos)
{
    __shared__ int sh[256];
    int t = threadIdx.x, base = blockIdx.x*1024 + t*4;
    int c[4]; int s = 0;
    #pragma unroll
    for (int j = 0; j < 4; j++) { int i = base+j; c[j] = (i < n) ? cnt[i] : 0; s += c[j]; }
    sh[t] = s; __syncthreads();
    for (int off = 1; off < 256; off <<= 1) {
        int u = t >= off ? sh[t-off] : 0;
        __syncthreads();
        sh[t] += u;
        __syncthreads();
    }
    int run = (t ? sh[t-1] : 0) + part[blockIdx.x];
    #pragma unroll
    for (int j = 0; j < 4; j++) {
        int i = base+j;
        if (i < n) { rowptr[i] = run; pos[i] = run; }
        run += c[j];
    }
}
__global__ void k_scatter(const int* __restrict__ src, const int* __restrict__ dst, int ne,
                          int* __restrict__ pos, int* __restrict__ srcs)
{
    int i = blockIdx.x*blockDim.x + threadIdx.x;
    if (i >= ne) return;
    int p = atomicAdd(&pos[dst[i]], 1);
    srcs[p] = src[i];
}
__global__ void k_deginv(const int* __restrict__ rowptr, float* __restrict__ dinv, int n)
{
    int i = blockIdx.x*blockDim.x + threadIdx.x;
    if (i < n) dinv[i] = rsqrtf(fmaxf((float)(rowptr[i+1]-rowptr[i]), 1.f));
}
__global__ void k_scatter_norm(const int* __restrict__ src, const int* __restrict__ dst, int ne,
                               int* __restrict__ pos, const float* __restrict__ dinv,
                               int* __restrict__ srcs, float* __restrict__ normv)
{
    int i = blockIdx.x*blockDim.x + threadIdx.x;
    if (i >= ne) return;
    int s = src[i], d = dst[i];
    int p = atomicAdd(&pos[d], 1);
    srcs[p] = s;
    normv[p] = dinv[s]*dinv[d];
}

// ========== node-parallel GAT aggregation (16 lanes per dst node, 4-edge MLP) ==========
__global__ void k_gat_node(const int* __restrict__ rowptr, const int* __restrict__ srcs,
                           const float* __restrict__ fs, const float* __restrict__ fd,
                           const float* __restrict__ attn, float* __restrict__ out, int n)
{
    int w = (blockIdx.x*blockDim.x + threadIdx.x) >> 4;
    int l = threadIdx.x & 15;
    unsigned mask = 0xFFFFu << (threadIdx.x & 16);
    if (w >= n) return;
    int beg = rowptr[w], end = rowptr[w+1];
    float4 fdv = ((const float4*)fd)[(size_t)w*16 + l];
    float4 at  = ((const float4*)attn)[l];
    float4 acc = make_float4(0.f,0.f,0.f,0.f);
    float den = 0.f;
    int e = beg;
    for (; e+4 <= end; e += 4) {
        int s0 = srcs[e], s1 = srcs[e+1], s2 = srcs[e+2], s3 = srcs[e+3];
        float4 f0 = ((const float4*)fs)[(size_t)s0*16 + l];
        float4 f1 = ((const float4*)fs)[(size_t)s1*16 + l];
        float4 f2 = ((const float4*)fs)[(size_t)s2*16 + l];
        float4 f3 = ((const float4*)fs)[(size_t)s3*16 + l];
        float t0 = lrelu(f0.x+fdv.x,0.2f)*at.x + lrelu(f0.y+fdv.y,0.2f)*at.y
                 + lrelu(f0.z+fdv.z,0.2f)*at.z + lrelu(f0.w+fdv.w,0.2f)*at.w;
        float t1 = lrelu(f1.x+fdv.x,0.2f)*at.x + lrelu(f1.y+fdv.y,0.2f)*at.y
                 + lrelu(f1.z+fdv.z,0.2f)*at.z + lrelu(f1.w+fdv.w,0.2f)*at.w;
        float t2 = lrelu(f2.x+fdv.x,0.2f)*at.x + lrelu(f2.y+fdv.y,0.2f)*at.y
                 + lrelu(f2.z+fdv.z,0.2f)*at.z + lrelu(f2.w+fdv.w,0.2f)*at.w;
        float t3 = lrelu(f3.x+fdv.x,0.2f)*at.x + lrelu(f3.y+fdv.y,0.2f)*at.y
                 + lrelu(f3.z+fdv.z,0.2f)*at.z + lrelu(f3.w+fdv.w,0.2f)*at.w;
        #pragma unroll
        for (int o = 8; o; o >>= 1) {
            t0 += __shfl_xor_sync(mask, t0, o, 16);
            t1 += __shfl_xor_sync(mask, t1, o, 16);
            t2 += __shfl_xor_sync(mask, t2, o, 16);
            t3 += __shfl_xor_sync(mask, t3, o, 16);
        }
        float e0 = __expf(t0), e1 = __expf(t1), e2 = __expf(t2), e3 = __expf(t3);
        den += (e0 + e1) + (e2 + e3);
        acc.x += e0*f0.x + e1*f1.x + e2*f2.x + e3*f3.x;
        acc.y += e0*f0.y + e1*f1.y + e2*f2.y + e3*f3.y;
        acc.z += e0*f0.z + e1*f1.z + e2*f2.z + e3*f3.z;
        acc.w += e0*f0.w + e1*f1.w + e2*f2.w + e3*f3.w;
    }
    for (; e < end; e++) {
        int s0 = srcs[e];
        float4 f0 = ((const float4*)fs)[(size_t)s0*16 + l];
        float t0 = lrelu(f0.x+fdv.x,0.2f)*at.x + lrelu(f0.y+fdv.y,0.2f)*at.y
                 + lrelu(f0.z+fdv.z,0.2f)*at.z + lrelu(f0.w+fdv.w,0.2f)*at.w;
        #pragma unroll
        for (int o = 8; o; o >>= 1) t0 += __shfl_xor_sync(mask, t0, o, 16);
        float e0 = __expf(t0);
        den += e0;
        acc.x += e0*f0.x; acc.y += e0*f0.y; acc.z += e0*f0.z; acc.w += e0*f0.w;
    }
    float inv = den > 0.f ? 1.f/den : 0.f;
    ((float4*)out)[(size_t)w*16 + l] =
        make_float4(lrelu(acc.x*inv,0.01f), lrelu(acc.y*inv,0.01f),
                    lrelu(acc.z*inv,0.01f), lrelu(acc.w*inv,0.01f));
}

// node-parallel lhat (16 lanes/node, 4-edge MLP)
__global__ void k_lhat_node(const int* __restrict__ rowptr, const int* __restrict__ srcs,
                            const float* __restrict__ normv, const float* __restrict__ v,
                            const float* __restrict__ lamp, const float* __restrict__ t0arr,
                            float* __restrict__ out, int n)
{
    int w = (blockIdx.x*blockDim.x + threadIdx.x) >> 4;
    int l = threadIdx.x & 15;
    if (w >= n) return;
    int beg = rowptr[w], end = rowptr[w+1];
    float4 acc = make_float4(0.f,0.f,0.f,0.f);
    int e = beg;
    for (; e+4 <= end; e += 4) {
        int s0 = srcs[e], s1 = srcs[e+1], s2 = srcs[e+2], s3 = srcs[e+3];
        float n0 = normv[e], n1 = normv[e+1], n2 = normv[e+2], n3 = normv[e+3];
        float4 f0 = ((const float4*)v)[(size_t)s0*16 + l];
        float4 f1 = ((const float4*)v)[(size_t)s1*16 + l];
        float4 f2 = ((const float4*)v)[(size_t)s2*16 + l];
        float4 f3 = ((const float4*)v)[(size_t)s3*16 + l];
        acc.x += (n0*f0.x + n1*f1.x) + (n2*f2.x + n3*f3.x);
        acc.y += (n0*f0.y + n1*f1.y) + (n2*f2.y + n3*f3.y);
        acc.z += (n0*f0.z + n1*f1.z) + (n2*f2.z + n3*f3.z);
        acc.w += (n0*f0.w + n1*f1.w) + (n2*f2.w + n3*f3.w);
    }
    for (; e < end; e++) {
        int s0 = srcs[e];
        float n0 = normv[e];
        float4 f0 = ((const float4*)v)[(size_t)s0*16 + l];
        acc.x += n0*f0.x; acc.y += n0*f0.y; acc.z += n0*f0.z; acc.w += n0*f0.w;
    }
    float c = 2.f / __ldg(lamp);
    float4 vv = ((const float4*)v)[(size_t)w*16 + l];
    float4 o = make_float4(c*(vv.x-acc.x)-vv.x, c*(vv.y-acc.y)-vv.y,
                           c*(vv.z-acc.z)-vv.z, c*(vv.w-acc.w)-vv.w);
    if (t0arr) {
        float4 t0 = ((const float4*)t0arr)[(size_t)w*16 + l];
        o = make_float4(2.f*o.x-t0.x, 2.f*o.y-t0.y, 2.f*o.z-t0.z, 2.f*o.w-t0.w);
    }
    ((float4*)out)[(size_t)w*16 + l] = o;
}

// ---------------- misc ----------------
// fused soc build: soc[r] = (sum(i2u[r]) != 0) ? i2u[r] : uie[r]
__global__ void k_socmerge(const float* __restrict__ i2u, const float* __restrict__ uie,
                           const int* __restrict__ ids, float* __restrict__ soc, int n)
{
    int t = blockIdx.x*blockDim.x + threadIdx.x;
    int r = t >> 4, l = t & 15;
    if (r >= n) return;
    // ids is the identity permutation's target list (i2u_ids = arange(PRED)), but we
    // honor it anyway: thread group r computes i2u row r and writes soc[ids[r]].
    float4 v = ((const float4*)i2u)[(size_t)r*16 + l];
    float s = v.x + v.y + v.z + v.w;
    unsigned mask = 0xFFFFu << (threadIdx.x & 16);
    #pragma unroll
    for (int o = 8; o; o >>= 1) s += __shfl_xor_sync(mask, s, o, 16);
    int tr = ids[r];
    float4 u = ((const float4*)uie)[(size_t)tr*16 + l];
    ((float4*)soc)[(size_t)tr*16 + l] = (s != 0.f) ? v : u;
}
__global__ void k_softmul2(const float* __restrict__ hP, const float* __restrict__ hS,
                           float* __restrict__ mAP, float* __restrict__ mAS, int n)
{
    int t = blockIdx.x*blockDim.x + threadIdx.x;
    int r = t >> 4, l = t & 15;
    unsigned mask = 0xFFFFu << (threadIdx.x & 16);
    if (r >= n) return;
    size_t base = (size_t)r*16 + l;
    float4 p = ((const float4*)hP)[base];
    float4 s = ((const float4*)hS)[base];
    float mp = fmaxf(fmaxf(p.x,p.y), fmaxf(p.z,p.w));
    float ms = fmaxf(fmaxf(s.x,s.y), fmaxf(s.z,s.w));
    #pragma unroll
    for (int o = 8; o; o >>= 1) {
        mp = fmaxf(mp, __shfl_xor_sync(mask, mp, o, 16));
        ms = fmaxf(ms, __shfl_xor_sync(mask, ms, o, 16));
    }
    float4 eP = make_float4(__expf(p.x-mp), __expf(p.y-mp), __expf(p.z-mp), __expf(p.w-mp));
    float4 eS = make_float4(__expf(s.x-ms), __expf(s.y-ms), __expf(s.z-ms), __expf(s.w-ms));
    float sp = eP.x+eP.y+eP.z+eP.w;
    float ss = eS.x+eS.y+eS.z+eS.w;
    #pragma unroll
    for (int o = 8; o; o >>= 1) {
        sp += __shfl_xor_sync(mask, sp, o, 16);
        ss += __shfl_xor_sync(mask, ss, o, 16);
    }
    float ip = 1.f/sp, is = 1.f/ss;
    float4 hm = make_float4(p.x*s.x, p.y*s.y, p.z*s.z, p.w*s.w);
    ((float4*)mAP)[base] = make_float4(hm.x*eP.x*ip, hm.y*eP.y*ip, hm.z*eP.z*ip, hm.w*eP.w*ip);
    ((float4*)mAS)[base] = make_float4(hm.x*eS.x*is, hm.y*eS.y*is, hm.z*eS.z*is, hm.w*eS.w*is);
}

// ---------------- host-side composition ----------------
struct Bufs {
    float *ebn,*uie,*fs,*fd,*gout,*u2i,*rc,*T1,*T2,*ch,*ch2,*i2u,*soc,*sie,
          *uitem,*huP,*huS,*mA,*mA2,*z,*stat,*deginv,*normv;
    int *srcs,*rowptr,*cnt,*pos,*part;
};
static void get_bufs(Bufs& B) {
    cudaGetSymbolAddress((void**)&B.ebn,  g_ebn);
    cudaGetSymbolAddress((void**)&B.uie,  g_uie);
    cudaGetSymbolAddress((void**)&B.fs,   g_fs);
    cudaGetSymbolAddress((void**)&B.fd,   g_fd);
    cudaGetSymbolAddress((void**)&B.gout, g_gout);
    cudaGetSymbolAddress((void**)&B.u2i,  g_u2i);
    cudaGetSymbolAddress((void**)&B.rc,   g_rc);
    cudaGetSymbolAddress((void**)&B.T1,   g_T1);
    cudaGetSymbolAddress((void**)&B.T2,   g_T2);
    cudaGetSymbolAddress((void**)&B.ch,   g_ch);
    cudaGetSymbolAddress((void**)&B.ch2,  g_ch2);
    cudaGetSymbolAddress((void**)&B.i2u,  g_i2u);
    cudaGetSymbolAddress((void**)&B.soc,  g_soc);
    cudaGetSymbolAddress((void**)&B.sie,  g_sie);
    cudaGetSymbolAddress((void**)&B.uitem,g_uitem);
    cudaGetSymbolAddress((void**)&B.huP,  g_huP);
    cudaGetSymbolAddress((void**)&B.huS,  g_huS);
    cudaGetSymbolAddress((void**)&B.mA,   g_mA);
    cudaGetSymbolAddress((void**)&B.mA2,  g_mA2);
    cudaGetSymbolAddress((void**)&B.z,    g_z);
    cudaGetSymbolAddress((void**)&B.stat, g_stat);
    cudaGetSymbolAddress((void**)&B.deginv, g_deginv);
    cudaGetSymbolAddress((void**)&B.normv,  g_normv);
    cudaGetSymbolAddress((void**)&B.srcs,   g_srcs);
    cudaGetSymbolAddress((void**)&B.rowptr, g_rowptr);
    cudaGetSymbolAddress((void**)&B.cnt,    g_cnt);
    cudaGetSymbolAddress((void**)&B.pos,    g_pos);
    cudaGetSymbolAddress((void**)&B.part,   g_part);
}

static void sort_graph(Bufs& B, const int* src, const int* dst, int ne, int n,
                       int* rowptr, int* srcs, bool with_norm)
{
    cudaMemsetAsync(B.cnt, 0, (size_t)n*4);
    k_hist<<<ceil_div(ne,256),256>>>(dst, ne, B.cnt);
    int nb = ceil_div(n, 1024);
    k_scan_part<<<nb,256>>>(B.cnt, n, B.part);
    k_scan_top<<<1,256>>>(B.part, nb, rowptr + n);
    k_scan_final<<<nb,256>>>(B.cnt, B.part, n, rowptr, B.pos);
    if (with_norm) {
        k_deginv<<<ceil_div(n,256),256>>>(rowptr, B.deginv, n);
        k_scatter_norm<<<ceil_div(ne,256),256>>>(src, dst, ne, B.pos, B.deginv,
                                                 srcs, B.normv);
    } else {
        k_scatter<<<ceil_div(ne,256),256>>>(src, dst, ne, B.pos, srcs);
    }
}

static void run_gat(Bufs& B, const int* rowptr, const int* srcs,
                    const float* x, const int* ids, int n,
                    const float* Wl, const float* bl,
                    const float* Wr, const float* br,
                    const float* attn, float* out)
{
    k_gemm_dual<<<ceil_div(n,64),128>>>(x, ids, Wl, bl, B.fs, Wr, br, B.fd, n);
    k_gat_node<<<ceil_div(n*16,256),256>>>(rowptr, srcs, B.fs, B.fd, attn, out, n);
}

static void run_mlp(Bufs& B, const float* A, const float* Bx, const float* W,
                    const float* b, const float* g, const float* beta,
                    float* out, int n, float* stat)
{
    k_gemm_cat<<<ceil_div(n,64),128>>>(A, Bx, W, b, B.z, n, stat);
    k_bnapply<<<ceil_div(n*16,256),256>>>(B.z, stat, g, beta, out, n*16, 1.0f/n, 1);
}

extern "C" void kernel_launch(void* const* d_in, const int* in_sizes, int n_in,
                              void* d_out, int out_size)
{
    const float* emb      = (const float*)d_in[0];
    const float* bn0_g    = (const float*)d_in[1];
    const float* bn0_b    = (const float*)d_in[2];
    const float* gat_Wl   = (const float*)d_in[3];
    const float* gat_bl   = (const float*)d_in[4];
    const float* gat_Wr   = (const float*)d_in[5];
    const float* gat_br   = (const float*)d_in[6];
    const float* gat_attn = (const float*)d_in[7];
    const float* cheb_W   = (const float*)d_in[8];
    const float* cheb_b   = (const float*)d_in[9];
    const float* mlp_W    = (const float*)d_in[10];
    const float* mlp_b    = (const float*)d_in[11];
    const float* mlp_g    = (const float*)d_in[12];
    const float* mlp_beta = (const float*)d_in[13];
    const float* lam      = (const float*)d_in[14];
    const int* u2i_src = (const int*)d_in[15]; const int* u2i_dst = (const int*)d_in[16];
    const int* rc_src  = (const int*)d_in[17]; const int* rc_dst  = (const int*)d_in[18];
    const int* i2u_src = (const int*)d_in[19]; const int* i2u_dst = (const int*)d_in[20];
    const int* i2u_ids = (const int*)d_in[21];
    const int* sn_src  = (const int*)d_in[22]; const int* sn_dst  = (const int*)d_in[23];
    const int* snn_src = (const int*)d_in[24]; const int* snn_dst = (const int*)d_in[25];

    int ne_u2i = in_sizes[15], ne_rc = in_sizes[17], ne_i2u = in_sizes[19];
    int ne_sn  = in_sizes[22], ne_snn = in_sizes[24];

    float* out = (float*)d_out;
    Bufs B; get_bufs(B);

    int* rp_u2i = B.rowptr + 0*RPSZ; int* sc_u2i = B.srcs + 0;
    int* rp_rc  = B.rowptr + 1*RPSZ; int* sc_rc  = B.srcs + 1500000;
    int* rp_i2u = B.rowptr + 2*RPSZ; int* sc_i2u = B.srcs + 3000000;
    int* rp_sn  = B.rowptr + 3*RPSZ; int* sc_sn  = B.srcs + 4000000;
    int* rp_snn = B.rowptr + 4*RPSZ; int* sc_snn = B.srcs + 5000000;

    cudaMemsetAsync(B.stat, 0, 6*128*4);

    sort_graph(B, u2i_src, u2i_dst, ne_u2i, NUIN,   rp_u2i, sc_u2i, false);
    sort_graph(B, rc_src,  rc_dst,  ne_rc,  NUIN,   rp_rc,  sc_rc,  false);
    sort_graph(B, i2u_src, i2u_dst, ne_i2u, NPREDN, rp_i2u, sc_i2u, false);
    sort_graph(B, sn_src,  sn_dst,  ne_sn,  NPREDN, rp_sn,  sc_sn,  false);
    sort_graph(B, snn_src, snn_dst, ne_snn, NTOTN,  rp_snn, sc_snn, true);

    // 1. e = BN(emb); fused uie
    k_colstats<<<512,256>>>(emb, NNODESN, B.stat);
    k_bnapply_uie<<<ceil_div(NNODESN*16,256),256>>>(emb, B.stat, bn0_g, bn0_b,
                                                    B.ebn, B.uie, 1.0f/NNODESN);

    // 2. GAT0 (u2i), GAT1 (rc)
    run_gat(B, rp_u2i, sc_u2i, B.uie, nullptr, NUIN,
            gat_Wl+0*4096, gat_bl+0*64, gat_Wr+0*4096, gat_br+0*64, gat_attn+0*64, B.u2i);
    run_gat(B, rp_rc, sc_rc, B.u2i, nullptr, NUIN,
            gat_Wl+1*4096, gat_bl+1*64, gat_Wr+1*4096, gat_br+1*64, gat_attn+1*64, B.rc);

    // 3. GAT2 on su = uie[i2u_ids]
    run_gat(B, rp_i2u, sc_i2u, B.uie, i2u_ids, NPREDN,
            gat_Wl+2*4096, gat_bl+2*64, gat_Wr+2*4096, gat_br+2*64, gat_attn+2*64, B.i2u);

    // 4. soc (fused copy+mask-merge)
    k_socmerge<<<ceil_div(NPREDN*16,256),256>>>(B.i2u, B.uie, i2u_ids, B.soc, NPREDN);

    // 5. GAT3 (sn)
    run_gat(B, rp_sn, sc_sn, B.soc, nullptr, NPREDN,
            gat_Wl+3*4096, gat_bl+3*64, gat_Wr+3*4096, gat_br+3*64, gat_attn+3*64, B.sie);

    // 6. user_item_embed = mlp0([iie, sie])
    run_mlp(B, B.rc, B.sie, mlp_W+0*8192, mlp_b+0*64, mlp_g+0*64, mlp_beta+0*64,
            B.uitem, NPREDN, B.stat + 128);

    // 7. Cheb layer 1 (T0 = ebn[:TOTAL]); second lhat emits T2 = 2*lhat(T1)-T0
    k_lhat_node<<<ceil_div(NTOTN*16,256),256>>>(rp_snn, sc_snn, B.normv, B.ebn, lam,
                                                nullptr, B.T1, NTOTN);
    k_lhat_node<<<ceil_div(NTOTN*16,256),256>>>(rp_snn, sc_snn, B.normv, B.T1, lam,
                                                B.ebn, B.T2, NTOTN);
    k_gemm_cat3<<<ceil_div(NTOTN,64),128>>>(B.ebn, B.T1, B.T2, cheb_W, cheb_b, B.ch, NTOTN);

    // 8. Cheb layer 2
    k_lhat_node<<<ceil_div(NTOTN*16,256),256>>>(rp_snn, sc_snn, B.normv, B.ch, lam,
                                                nullptr, B.T1, NTOTN);
    k_lhat_node<<<ceil_div(NTOTN*16,256),256>>>(rp_snn, sc_snn, B.normv, B.T1, lam,
                                                B.ch, B.T2, NTOTN);
    k_gemm_cat3<<<ceil_div(NTOTN,64),128>>>(B.ch, B.T1, B.T2, cheb_W, cheb_b, B.ch2, NTOTN);

    // 9. GAT4 (snn)
    run_gat(B, rp_snn, sc_snn, B.ch2, nullptr, NTOTN,
            gat_Wl+4*4096, gat_bl+4*64, gat_Wr+4*4096, gat_br+4*64, gat_attn+4*64, B.gout);

    // 10. h_uP, h_uS
    run_mlp(B, B.uitem, B.ebn, mlp_W+1*8192, mlp_b+1*64, mlp_g+1*64, mlp_beta+1*64,
            B.huP, NPREDN, B.stat + 2*128);
    run_mlp(B, B.gout,  B.ebn, mlp_W+2*8192, mlp_b+2*64, mlp_g+2*64, mlp_beta+2*64,
            B.huS, NPREDN, B.stat + 3*128);

    // 11. fused gating + final MLPs
    k_softmul2<<<ceil_div(NPREDN*16,256),256>>>(B.huP, B.huS, B.mA, B.mA2, NPREDN);
    run_mlp(B, B.mA, B.huP, mlp_W+3*8192, mlp_b+3*64, mlp_g+3*64, mlp_beta+3*64,
            out, NPREDN, B.stat + 4*128);
    run_mlp(B, B.mA2, B.huS, mlp_W+4*8192, mlp_b+4*64, mlp_g+4*64, mlp_beta+4*64,
            out + (size_t)NPREDN*EMBD, NPREDN, B.stat + 5*128);
}

// round 15
// speedup vs baseline: 1.4024x; 1.4024x over previous
#include <cuda_runtime.h>
#include <math.h>

#define NPREDN 100000
#define NTOTN  120000
#define NUIN   200000
#define NNODESN 220000
#define EMBD 64
#define MAXE 1500000
#define RPSZ 200001
#define XSTRIDE 66   // transposed X tile row stride (floats): even -> 8B aligned pairs

typedef unsigned long long ull;

// ---------------- device scratch (static, no allocations) ----------------
__device__ float g_ebn[NNODESN*EMBD];
__device__ float g_uie[NUIN*EMBD];
__device__ float g_fs[NUIN*EMBD];
__device__ float g_fd[NUIN*EMBD];
__device__ float g_gout[NUIN*EMBD];
__device__ float g_u2i[NUIN*EMBD];
__device__ float g_rc[NUIN*EMBD];
__device__ float g_T1[NTOTN*EMBD];
__device__ float g_T2[NTOTN*EMBD];
__device__ float g_ch[NTOTN*EMBD];
__device__ float g_ch2[NTOTN*EMBD];
__device__ float g_i2u[NPREDN*EMBD];
__device__ float g_soc[NPREDN*EMBD];
__device__ float g_sie[NPREDN*EMBD];
__device__ float g_uitem[NPREDN*EMBD];
__device__ float g_huP[NPREDN*EMBD];
__device__ float g_huS[NPREDN*EMBD];
__device__ float g_mA[NPREDN*EMBD];
__device__ float g_mA2[NPREDN*EMBD];
__device__ float g_z[NPREDN*EMBD];
__device__ float g_stat[6*128];
// CSR sort scratch
__device__ int   g_srcs[7000000];
__device__ int   g_rowptr[5*RPSZ];
__device__ int   g_cnt[RPSZ];
__device__ int   g_pos[RPSZ];
__device__ int   g_part[256];
__device__ float g_deginv[NTOTN];
__device__ float g_normv[MAXE];

static inline int ceil_div(int a, int b) { return (a + b - 1) / b; }

__device__ __forceinline__ float lrelu(float v, float s) { return v > 0.f ? v : s*v; }

__device__ __forceinline__ ull dup_f(float x) {
    ull r; asm("mov.b64 %0, {%1,%1};" : "=l"(r) : "f"(x)); return r;
}
__device__ __forceinline__ float2 unpk(ull v) {
    float2 r; asm("mov.b64 {%0,%1}, %2;" : "=f"(r.x), "=f"(r.y) : "l"(v)); return r;
}
__device__ __forceinline__ void ffma2(ull& acc, ull a, ull b) {
    asm("fma.rn.f32x2 %0, %1, %2, %0;" : "+l"(acc) : "l"(a), "l"(b));
}

// ====== GEMM family: 64-row blocks, 128 threads, 8 rows x 4 cols per thread =======
__device__ __forceinline__ void load_x64_t(const float* __restrict__ X,
                                           const int* __restrict__ ids,
                                           float* Xt, int row0, int n, int tid)
{
    #pragma unroll
    for (int i = 0; i < 8; i++) {
        int idx = tid + i*128;
        int r = idx >> 4, c4 = idx & 15;
        int gr = row0 + r;
        float4 v = make_float4(0.f,0.f,0.f,0.f);
        if (gr < n) {
            int sr = ids ? ids[gr] : gr;
            v = ((const float4*)X)[(size_t)sr*16 + c4];
        }
        int k0 = c4*4;
        Xt[(k0+0)*XSTRIDE + r] = v.x;
        Xt[(k0+1)*XSTRIDE + r] = v.y;
        Xt[(k0+2)*XSTRIDE + r] = v.z;
        Xt[(k0+3)*XSTRIDE + r] = v.w;
    }
}
__device__ __forceinline__ void load_w64(const float* __restrict__ W, float* Ws, int tid)
{
    #pragma unroll
    for (int i = 0; i < 8; i++)
        ((float4*)Ws)[tid + i*128] = ((const float4*)W)[tid + i*128];
}

__device__ __forceinline__ void mm_f2t(const float* Xt, const float* Ws,
                                       ull acc[4][4], int tx, int ty)
{
    #pragma unroll 8
    for (int k = 0; k < 64; k++) {
        float4 b = *(const float4*)&Ws[k*64 + tx*4];
        ull b0 = dup_f(b.x), b1 = dup_f(b.y), b2 = dup_f(b.z), b3 = dup_f(b.w);
        const ull* ap = (const ull*)&Xt[k*XSTRIDE + ty*8];
        #pragma unroll
        for (int i = 0; i < 4; i++) {
            ull a = ap[i];
            ffma2(acc[i][0], a, b0);
            ffma2(acc[i][1], a, b1);
            ffma2(acc[i][2], a, b2);
            ffma2(acc[i][3], a, b3);
        }
    }
}

__device__ __forceinline__ void unpack_acc(ull acc[4][4], float f[8][4])
{
    #pragma unroll
    for (int i = 0; i < 4; i++) {
        #pragma unroll
        for (int j = 0; j < 4; j++) {
            float2 p = unpk(acc[i][j]);
            f[2*i][j]   = p.x;
            f[2*i+1][j] = p.y;
        }
    }
}

__device__ __forceinline__ void store8x4(float* __restrict__ Y, float f[8][4],
                                         const float* __restrict__ bias,
                                         int row0, int n, int tx, int ty, int act)
{
    float4 bb = bias ? ((const float4*)bias)[tx] : make_float4(0.f,0.f,0.f,0.f);
    #pragma unroll
    for (int i = 0; i < 8; i++) {
        int gr = row0 + ty*8 + i;
        if (gr < n) {
            float4 v = make_float4(f[i][0]+bb.x, f[i][1]+bb.y, f[i][2]+bb.z, f[i][3]+bb.w);
            if (act) { v.x=lrelu(v.x,0.01f); v.y=lrelu(v.y,0.01f);
                       v.z=lrelu(v.z,0.01f); v.w=lrelu(v.w,0.01f); }
            ((float4*)Y)[(size_t)gr*16 + tx] = v;
        }
    }
}

__device__ __forceinline__ void stats_epilogue(float f[8][4], float* sh,
                                               const float* __restrict__ bias,
                                               float* __restrict__ stat,
                                               int row0, int n, int tx, int ty, int tid)
{
    float4 bb = bias ? ((const float4*)bias)[tx] : make_float4(0.f,0.f,0.f,0.f);
    float s[4] = {0,0,0,0}, q[4] = {0,0,0,0};
    #pragma unroll
    for (int i = 0; i < 8; i++) {
        int gr = row0 + ty*8 + i;
        if (gr < n) {
            float v0 = f[i][0]+bb.x, v1 = f[i][1]+bb.y;
            float v2 = f[i][2]+bb.z, v3 = f[i][3]+bb.w;
            s[0]+=v0; s[1]+=v1; s[2]+=v2; s[3]+=v3;
            q[0]+=v0*v0; q[1]+=v1*v1; q[2]+=v2*v2; q[3]+=v3*v3;
        }
    }
    __syncthreads();
    #pragma unroll
    for (int k = 0; k < 4; k++) {
        sh[ty*128 + tx*8 + k]     = s[k];
        sh[ty*128 + tx*8 + 4 + k] = q[k];
    }
    __syncthreads();
    if (tid < 128) {
        float t = 0.f;
        #pragma unroll
        for (int w = 0; w < 8; w++) t += sh[w*128 + tid];
        int txx = tid >> 3, qq = tid & 7;
        int col = txx*4 + (qq & 3);
        atomicAdd(&stat[(qq < 4 ? col : 64 + col)], t);
    }
}

__global__ void __launch_bounds__(128) k_gemm_dual(
    const float* __restrict__ X, const int* __restrict__ ids,
    const float* __restrict__ W1, const float* __restrict__ b1, float* __restrict__ Y1,
    const float* __restrict__ W2, const float* __restrict__ b2, float* __restrict__ Y2,
    int n)
{
    __shared__ float Xt[64*XSTRIDE];
    __shared__ float Ws[4096];
    int tid = threadIdx.x, tx = tid & 15, ty = tid >> 4;
    int row0 = blockIdx.x * 64;
    load_x64_t(X, ids, Xt, row0, n, tid);
    load_w64(W1, Ws, tid);
    __syncthreads();
    {
        ull acc[4][4] = {};
        mm_f2t(Xt, Ws, acc, tx, ty);
        float f[8][4]; unpack_acc(acc, f);
        store8x4(Y1, f, b1, row0, n, tx, ty, 0);
    }
    __syncthreads();
    load_w64(W2, Ws, tid);
    __syncthreads();
    {
        ull acc[4][4] = {};
        mm_f2t(Xt, Ws, acc, tx, ty);
        float f[8][4]; unpack_acc(acc, f);
        store8x4(Y2, f, b2, row0, n, tx, ty, 0);
    }
}

__global__ void __launch_bounds__(128) k_gemm_cat(
    const float* __restrict__ A, const float* __restrict__ Bx,
    const float* __restrict__ W, const float* __restrict__ bias,
    float* __restrict__ Y, int n, float* __restrict__ stat)
{
    __shared__ float Xt[64*XSTRIDE];
    __shared__ float Ws[4096];
    int tid = threadIdx.x, tx = tid & 15, ty = tid >> 4;
    int row0 = blockIdx.x * 64;
    ull acc[4][4] = {};
    load_x64_t(A, nullptr, Xt, row0, n, tid);
    load_w64(W, Ws, tid);
    __syncthreads();
    mm_f2t(Xt, Ws, acc, tx, ty);
    __syncthreads();
    load_x64_t(Bx, nullptr, Xt, row0, n, tid);
    load_w64(W + 4096, Ws, tid);
    __syncthreads();
    mm_f2t(Xt, Ws, acc, tx, ty);
    float f[8][4]; unpack_acc(acc, f);
    store8x4(Y, f, bias, row0, n, tx, ty, 0);
    if (stat) stats_epilogue(f, Ws, bias, stat, row0, n, tx, ty, tid);
}

// cheb: Y = lrelu(X0@W0 + X1@W1 + X2c@W2 + bias); X2c pre-combined (2*lhat(T1)-T0)
__global__ void __launch_bounds__(128) k_gemm_cat3(
    const float* __restrict__ X0, const float* __restrict__ X1, const float* __restrict__ X2c,
    const float* __restrict__ W, const float* __restrict__ bias,
    float* __restrict__ Y, int n)
{
    __shared__ float Xt[64*XSTRIDE];
    __shared__ float Ws[4096];
    int tid = threadIdx.x, tx = tid & 15, ty = tid >> 4;
    int row0 = blockIdx.x * 64;
    ull acc[4][4] = {};
    load_x64_t(X0, nullptr, Xt, row0, n, tid);
    load_w64(W, Ws, tid);
    __syncthreads();
    mm_f2t(Xt, Ws, acc, tx, ty);
    __syncthreads();
    load_x64_t(X1, nullptr, Xt, row0, n, tid);
    load_w64(W + 4096, Ws, tid);
    __syncthreads();
    mm_f2t(Xt, Ws, acc, tx, ty);
    __syncthreads();
    load_x64_t(X2c, nullptr, Xt, row0, n, tid);
    load_w64(W + 8192, Ws, tid);
    __syncthreads();
    mm_f2t(Xt, Ws, acc, tx, ty);
    float f[8][4]; unpack_acc(acc, f);
    store8x4(Y, f, bias, row0, n, tx, ty, 1);
}

// ---------------- BN ----------------
__global__ void k_colstats(const float* __restrict__ X, int n, float* __restrict__ stat)
{
    int c  = threadIdx.x & 63;
    int tg = threadIdx.x >> 6;
    float s = 0.f, sq = 0.f;
    for (int r = blockIdx.x*4 + tg; r < n; r += gridDim.x*4) {
        float v = X[(size_t)r*64 + c];
        s += v; sq += v*v;
    }
    __shared__ float sh[4][128];
    sh[tg][c] = s; sh[tg][64+c] = sq;
    __syncthreads();
    if (tg == 0) {
        float ts = sh[0][c]+sh[1][c]+sh[2][c]+sh[3][c];
        float tq = sh[0][64+c]+sh[1][64+c]+sh[2][64+c]+sh[3][64+c];
        atomicAdd(&stat[c], ts);
        atomicAdd(&stat[64+c], tq);
    }
}

__device__ __forceinline__ float4 bn4(float4 x, float4 s1, float4 s2,
                                      float4 gg, float4 bb, float invn)
{
    float4 o;
    float mu = s1.x*invn, var = s2.x*invn - mu*mu;
    o.x = (x.x-mu)*rsqrtf(var+1e-5f)*gg.x + bb.x;
    mu = s1.y*invn; var = s2.y*invn - mu*mu;
    o.y = (x.y-mu)*rsqrtf(var+1e-5f)*gg.y + bb.y;
    mu = s1.z*invn; var = s2.z*invn - mu*mu;
    o.z = (x.z-mu)*rsqrtf(var+1e-5f)*gg.z + bb.z;
    mu = s1.w*invn; var = s2.w*invn - mu*mu;
    o.w = (x.w-mu)*rsqrtf(var+1e-5f)*gg.w + bb.w;
    return o;
}

__global__ void k_bnapply(const float* __restrict__ X, const float* __restrict__ stat,
                          const float* __restrict__ g, const float* __restrict__ b,
                          float* __restrict__ Y, int nq, float invn, int act)
{
    int i = blockIdx.x*blockDim.x + threadIdx.x;
    if (i >= nq) return;
    int c4 = i & 15;
    float4 o = bn4(((const float4*)X)[i], ((const float4*)stat)[c4],
                   ((const float4*)stat)[16+c4], ((const float4*)g)[c4],
                   ((const float4*)b)[c4], invn);
    if (act) { o.x=lrelu(o.x,0.01f); o.y=lrelu(o.y,0.01f);
               o.z=lrelu(o.z,0.01f); o.w=lrelu(o.w,0.01f); }
    ((float4*)Y)[i] = o;
}

__global__ void k_bnapply_uie(const float* __restrict__ X, const float* __restrict__ stat,
                              const float* __restrict__ g, const float* __restrict__ b,
                              float* __restrict__ ebn, float* __restrict__ uie, float invn)
{
    int i = blockIdx.x*blockDim.x + threadIdx.x;
    if (i >= NNODESN*16) return;
    int c4 = i & 15;
    float4 o = bn4(((const float4*)X)[i], ((const float4*)stat)[c4],
                   ((const float4*)stat)[16+c4], ((const float4*)g)[c4],
                   ((const float4*)b)[c4], invn);
    ((float4*)ebn)[i] = o;
    int row = i >> 4;
    if (row < NPREDN) ((float4*)uie)[i] = o;
    else if (row >= NNODESN - 100000)
        ((float4*)uie)[(size_t)(row - (NNODESN - NUIN))*16 + c4] = o;
}

// ================= counting sort by dst (CSR build) =================
__global__ void k_hist(const int* __restrict__ dst, int ne, int* __restrict__ cnt)
{
    int i = blockIdx.x*blockDim.x + threadIdx.x;
    if (i < ne) atomicAdd(&cnt[dst[i]], 1);
}
__global__ void k_scan_part(const int* __restrict__ cnt, int n, int* __restrict__ part)
{
    __shared__ int sh[256];
    int t = threadIdx.x, base = blockIdx.x*1024 + t*4;
    int s = 0;
    #pragma unroll
    for (int j = 0; j < 4; j++) { int i = base+j; if (i < n) s += cnt[i]; }
    sh[t] = s; __syncthreads();
    #pragma unroll
    for (int off = 128; off; off >>= 1) {
        if (t < off) sh[t] += sh[t+off];
        __syncthreads();
    }
    if (!t) part[blockIdx.x] = sh[0];
}
__global__ void k_scan_top(int* __restrict__ part, int nb, int* __restrict__ totptr)
{
    __shared__ int sh[256];
    int t = threadIdx.x;
    int v = t < nb ? part[t] : 0;
    sh[t] = v; __syncthreads();
    for (int off = 1; off < 256; off <<= 1) {
        int u = t >= off ? sh[t-off] : 0;
        __syncthreads();
        sh[t] += u;
        __syncthreads();
    }
    int excl = t ? sh[t-1] : 0;
    if (t < nb) part[t] = excl;
    if (t == 255) *totptr = sh[255];
}
__global__ void k_scan_final(const int* __restrict__ cnt, const int* __restrict__ part, int n,
                             int* __restrict__ rowptr, int* __restrict__ pos)
{
    __shared__ int sh[256];
    int t = threadIdx.x, base = blockIdx.x*1024 + t*4;
    int c[4]; int s = 0;
    #pragma unroll
    for (int j = 0; j < 4; j++) { int i = base+j; c[j] = (i < n) ? cnt[i] : 0; s += c[j]; }
    sh[t] = s; __syncthreads();
    for (int off = 1; off < 256; off <<= 1) {
        int u = t >= off ? sh[t-off] : 0;
        __syncthreads();
        sh[t] += u;
        __syncthreads();
    }
    int run = (t ? sh[t-1] : 0) + part[blockIdx.x];
    #pragma unroll
    for (int j = 0; j < 4; j++) {
        int i = base+j;
        if (i < n) { rowptr[i] = run; pos[i] = run; }
        run += c[j];
    }
}
__global__ void k_scatter(const int* __restrict__ src, const int* __restrict__ dst, int ne,
                          int* __restrict__ pos, int* __restrict__ srcs)
{
    int i = blockIdx.x*blockDim.x + threadIdx.x;
    if (i >= ne) return;
    int p = atomicAdd(&pos[dst[i]], 1);
    srcs[p] = src[i];
}
__global__ void k_deginv(const int* __restrict__ rowptr, float* __restrict__ dinv, int n)
{
    int i = blockIdx.x*blockDim.x + threadIdx.x;
    if (i < n) dinv[i] = rsqrtf(fmaxf((float)(rowptr[i+1]-rowptr[i]), 1.f));
}
__global__ void k_scatter_norm(const int* __restrict__ src, const int* __restrict__ dst, int ne,
                               int* __restrict__ pos, const float* __restrict__ dinv,
                               int* __restrict__ srcs, float* __restrict__ normv)
{
    int i = blockIdx.x*blockDim.x + threadIdx.x;
    if (i >= ne) return;
    int s = src[i], d = dst[i];
    int p = atomicAdd(&pos[d], 1);
    srcs[p] = s;
    normv[p] = dinv[s]*dinv[d];
}

// ========== node-parallel GAT aggregation (16 lanes per dst node, 4-edge MLP) ==========
__global__ void k_gat_node(const int* __restrict__ rowptr, const int* __restrict__ srcs,
                           const float* __restrict__ fs, const float* __restrict__ fd,
                           const float* __restrict__ attn, float* __restrict__ out, int n)
{
    int w = (blockIdx.x*blockDim.x + threadIdx.x) >> 4;
    int l = threadIdx.x & 15;
    unsigned mask = 0xFFFFu << (threadIdx.x & 16);
    if (w >= n) return;
    int beg = rowptr[w], end = rowptr[w+1];
    float4 fdv = ((const float4*)fd)[(size_t)w*16 + l];
    float4 at  = ((const float4*)attn)[l];
    float4 acc = make_float4(0.f,0.f,0.f,0.f);
    float den = 0.f;
    int e = beg;
    for (; e+4 <= end; e += 4) {
        int s0 = srcs[e], s1 = srcs[e+1], s2 = srcs[e+2], s3 = srcs[e+3];
        float4 f0 = ((const float4*)fs)[(size_t)s0*16 + l];
        float4 f1 = ((const float4*)fs)[(size_t)s1*16 + l];
        float4 f2 = ((const float4*)fs)[(size_t)s2*16 + l];
        float4 f3 = ((const float4*)fs)[(size_t)s3*16 + l];
        float t0 = lrelu(f0.x+fdv.x,0.2f)*at.x + lrelu(f0.y+fdv.y,0.2f)*at.y
                 + lrelu(f0.z+fdv.z,0.2f)*at.z + lrelu(f0.w+fdv.w,0.2f)*at.w;
        float t1 = lrelu(f1.x+fdv.x,0.2f)*at.x + lrelu(f1.y+fdv.y,0.2f)*at.y
                 + lrelu(f1.z+fdv.z,0.2f)*at.z + lrelu(f1.w+fdv.w,0.2f)*at.w;
        float t2 = lrelu(f2.x+fdv.x,0.2f)*at.x + lrelu(f2.y+fdv.y,0.2f)*at.y
                 + lrelu(f2.z+fdv.z,0.2f)*at.z + lrelu(f2.w+fdv.w,0.2f)*at.w;
        float t3 = lrelu(f3.x+fdv.x,0.2f)*at.x + lrelu(f3.y+fdv.y,0.2f)*at.y
                 + lrelu(f3.z+fdv.z,0.2f)*at.z + lrelu(f3.w+fdv.w,0.2f)*at.w;
        #pragma unroll
        for (int o = 8; o; o >>= 1) {
            t0 += __shfl_xor_sync(mask, t0, o, 16);
            t1 += __shfl_xor_sync(mask, t1, o, 16);
            t2 += __shfl_xor_sync(mask, t2, o, 16);
            t3 += __shfl_xor_sync(mask, t3, o, 16);
        }
        float e0 = __expf(t0), e1 = __expf(t1), e2 = __expf(t2), e3 = __expf(t3);
        den += (e0 + e1) + (e2 + e3);
        acc.x += e0*f0.x + e1*f1.x + e2*f2.x + e3*f3.x;
        acc.y += e0*f0.y + e1*f1.y + e2*f2.y + e3*f3.y;
        acc.z += e0*f0.z + e1*f1.z + e2*f2.z + e3*f3.z;
        acc.w += e0*f0.w + e1*f1.w + e2*f2.w + e3*f3.w;
    }
    for (; e < end; e++) {
        int s0 = srcs[e];
        float4 f0 = ((const float4*)fs)[(size_t)s0*16 + l];
        float t0 = lrelu(f0.x+fdv.x,0.2f)*at.x + lrelu(f0.y+fdv.y,0.2f)*at.y
                 + lrelu(f0.z+fdv.z,0.2f)*at.z + lrelu(f0.w+fdv.w,0.2f)*at.w;
        #pragma unroll
        for (int o = 8; o; o >>= 1) t0 += __shfl_xor_sync(mask, t0, o, 16);
        float e0 = __expf(t0);
        den += e0;
        acc.x += e0*f0.x; acc.y += e0*f0.y; acc.z += e0*f0.z; acc.w += e0*f0.w;
    }
    float inv = den > 0.f ? 1.f/den : 0.f;
    ((float4*)out)[(size_t)w*16 + l] =
        make_float4(lrelu(acc.x*inv,0.01f), lrelu(acc.y*inv,0.01f),
                    lrelu(acc.z*inv,0.01f), lrelu(acc.w*inv,0.01f));
}

// node-parallel lhat (16 lanes/node, 4-edge MLP)
__global__ void k_lhat_node(const int* __restrict__ rowptr, const int* __restrict__ srcs,
                            const float* __restrict__ normv, const float* __restrict__ v,
                            const float* __restrict__ lamp, const float* __restrict__ t0arr,
                            float* __restrict__ out, int n)
{
    int w = (blockIdx.x*blockDim.x + threadIdx.x) >> 4;
    int l = threadIdx.x & 15;
    if (w >= n) return;
    int beg = rowptr[w], end = rowptr[w+1];
    float4 acc = make_float4(0.f,0.f,0.f,0.f);
    int e = beg;
    for (; e+4 <= end; e += 4) {
        int s0 = srcs[e], s1 = srcs[e+1], s2 = srcs[e+2], s3 = srcs[e+3];
        float n0 = normv[e], n1 = normv[e+1], n2 = normv[e+2], n3 = normv[e+3];
        float4 f0 = ((const float4*)v)[(size_t)s0*16 + l];
        float4 f1 = ((const float4*)v)[(size_t)s1*16 + l];
        float4 f2 = ((const float4*)v)[(size_t)s2*16 + l];
        float4 f3 = ((const float4*)v)[(size_t)s3*16 + l];
        acc.x += (n0*f0.x + n1*f1.x) + (n2*f2.x + n3*f3.x);
        acc.y += (n0*f0.y + n1*f1.y) + (n2*f2.y + n3*f3.y);
        acc.z += (n0*f0.z + n1*f1.z) + (n2*f2.z + n3*f3.z);
        acc.w += (n0*f0.w + n1*f1.w) + (n2*f2.w + n3*f3.w);
    }
    for (; e < end; e++) {
        int s0 = srcs[e];
        float n0 = normv[e];
        float4 f0 = ((const float4*)v)[(size_t)s0*16 + l];
        acc.x += n0*f0.x; acc.y += n0*f0.y; acc.z += n0*f0.z; acc.w += n0*f0.w;
    }
    float c = 2.f / __ldg(lamp);
    float4 vv = ((const float4*)v)[(size_t)w*16 + l];
    float4 o = make_float4(c*(vv.x-acc.x)-vv.x, c*(vv.y-acc.y)-vv.y,
                           c*(vv.z-acc.z)-vv.z, c*(vv.w-acc.w)-vv.w);
    if (t0arr) {
        float4 t0 = ((const float4*)t0arr)[(size_t)w*16 + l];
        o = make_float4(2.f*o.x-t0.x, 2.f*o.y-t0.y, 2.f*o.z-t0.z, 2.f*o.w-t0.w);
    }
    ((float4*)out)[(size_t)w*16 + l] = o;
}

// ---------------- misc ----------------
__global__ void k_copy4(float* __restrict__ y, const float* __restrict__ x, int nq)
{
    int i = blockIdx.x*blockDim.x + threadIdx.x;
    if (i < nq) ((float4*)y)[i] = ((const float4*)x)[i];
}
__global__ void k_soc(const float* __restrict__ i2u, const int* __restrict__ ids,
                      float* __restrict__ soc, int n)
{
    int t = blockIdx.x*blockDim.x + threadIdx.x;
    int r = t >> 4, l = t & 15;
    if (r >= n) return;
    float4 v = ((const float4*)i2u)[(size_t)r*16 + l];
    float s = v.x + v.y + v.z + v.w;
    unsigned mask = 0xFFFFu << (threadIdx.x & 16);
    #pragma unroll
    for (int o = 8; o; o >>= 1) s += __shfl_xor_sync(mask, s, o, 16);
    if (s != 0.f) {
        int tr = ids[r];
        ((float4*)soc)[(size_t)tr*16 + l] = v;
    }
}
__global__ void k_softmul2(const float* __restrict__ hP, const float* __restrict__ hS,
                           float* __restrict__ mAP, float* __restrict__ mAS, int n)
{
    int t = blockIdx.x*blockDim.x + threadIdx.x;
    int r = t >> 4, l = t & 15;
    unsigned mask = 0xFFFFu << (threadIdx.x & 16);
    if (r >= n) return;
    size_t base = (size_t)r*16 + l;
    float4 p = ((const float4*)hP)[base];
    float4 s = ((const float4*)hS)[base];
    float mp = fmaxf(fmaxf(p.x,p.y), fmaxf(p.z,p.w));
    float ms = fmaxf(fmaxf(s.x,s.y), fmaxf(s.z,s.w));
    #pragma unroll
    for (int o = 8; o; o >>= 1) {
        mp = fmaxf(mp, __shfl_xor_sync(mask, mp, o, 16));
        ms = fmaxf(ms, __shfl_xor_sync(mask, ms, o, 16));
    }
    float4 eP = make_float4(__expf(p.x-mp), __expf(p.y-mp), __expf(p.z-mp), __expf(p.w-mp));
    float4 eS = make_float4(__expf(s.x-ms), __expf(s.y-ms), __expf(s.z-ms), __expf(s.w-ms));
    float sp = eP.x+eP.y+eP.z+eP.w;
    float ss = eS.x+eS.y+eS.z+eS.w;
    #pragma unroll
    for (int o = 8; o; o >>= 1) {
        sp += __shfl_xor_sync(mask, sp, o, 16);
        ss += __shfl_xor_sync(mask, ss, o, 16);
    }
    float ip = 1.f/sp, is = 1.f/ss;
    float4 hm = make_float4(p.x*s.x, p.y*s.y, p.z*s.z, p.w*s.w);
    ((float4*)mAP)[base] = make_float4(hm.x*eP.x*ip, hm.y*eP.y*ip, hm.z*eP.z*ip, hm.w*eP.w*ip);
    ((float4*)mAS)[base] = make_float4(hm.x*eS.x*is, hm.y*eS.y*is, hm.z*eS.z*is, hm.w*eS.w*is);
}

// ---------------- host-side composition ----------------
struct Bufs {
    float *ebn,*uie,*fs,*fd,*gout,*u2i,*rc,*T1,*T2,*ch,*ch2,*i2u,*soc,*sie,
          *uitem,*huP,*huS,*mA,*mA2,*z,*stat,*deginv,*normv;
    int *srcs,*rowptr,*cnt,*pos,*part;
};
static void get_bufs(Bufs& B) {
    cudaGetSymbolAddress((void**)&B.ebn,  g_ebn);
    cudaGetSymbolAddress((void**)&B.uie,  g_uie);
    cudaGetSymbolAddress((void**)&B.fs,   g_fs);
    cudaGetSymbolAddress((void**)&B.fd,   g_fd);
    cudaGetSymbolAddress((void**)&B.gout, g_gout);
    cudaGetSymbolAddress((void**)&B.u2i,  g_u2i);
    cudaGetSymbolAddress((void**)&B.rc,   g_rc);
    cudaGetSymbolAddress((void**)&B.T1,   g_T1);
    cudaGetSymbolAddress((void**)&B.T2,   g_T2);
    cudaGetSymbolAddress((void**)&B.ch,   g_ch);
    cudaGetSymbolAddress((void**)&B.ch2,  g_ch2);
    cudaGetSymbolAddress((void**)&B.i2u,  g_i2u);
    cudaGetSymbolAddress((void**)&B.soc,  g_soc);
    cudaGetSymbolAddress((void**)&B.sie,  g_sie);
    cudaGetSymbolAddress((void**)&B.uitem,g_uitem);
    cudaGetSymbolAddress((void**)&B.huP,  g_huP);
    cudaGetSymbolAddress((void**)&B.huS,  g_huS);
    cudaGetSymbolAddress((void**)&B.mA,   g_mA);
    cudaGetSymbolAddress((void**)&B.mA2,  g_mA2);
    cudaGetSymbolAddress((void**)&B.z,    g_z);
    cudaGetSymbolAddress((void**)&B.stat, g_stat);
    cudaGetSymbolAddress((void**)&B.deginv, g_deginv);
    cudaGetSymbolAddress((void**)&B.normv,  g_normv);
    cudaGetSymbolAddress((void**)&B.srcs,   g_srcs);
    cudaGetSymbolAddress((void**)&B.rowptr, g_rowptr);
    cudaGetSymbolAddress((void**)&B.cnt,    g_cnt);
    cudaGetSymbolAddress((void**)&B.pos,    g_pos);
    cudaGetSymbolAddress((void**)&B.part,   g_part);
}

static void sort_graph(Bufs& B, const int* src, const int* dst, int ne, int n,
                       int* rowptr, int* srcs, bool with_norm)
{
    cudaMemsetAsync(B.cnt, 0, (size_t)n*4);
    k_hist<<<ceil_div(ne,256),256>>>(dst, ne, B.cnt);
    int nb = ceil_div(n, 1024);
    k_scan_part<<<nb,256>>>(B.cnt, n, B.part);
    k_scan_top<<<1,256>>>(B.part, nb, rowptr + n);
    k_scan_final<<<nb,256>>>(B.cnt, B.part, n, rowptr, B.pos);
    if (with_norm) {
        k_deginv<<<ceil_div(n,256),256>>>(rowptr, B.deginv, n);
        k_scatter_norm<<<ceil_div(ne,256),256>>>(src, dst, ne, B.pos, B.deginv,
                                                 srcs, B.normv);
    } else {
        k_scatter<<<ceil_div(ne,256),256>>>(src, dst, ne, B.pos, srcs);
    }
}

static void run_gat(Bufs& B, const int* rowptr, const int* srcs,
                    const float* x, const int* ids, int n,
                    const float* Wl, const float* bl,
                    const float* Wr, const float* br,
                    const float* attn, float* out)
{
    k_gemm_dual<<<ceil_div(n,64),128>>>(x, ids, Wl, bl, B.fs, Wr, br, B.fd, n);
    k_gat_node<<<ceil_div(n*16,256),256>>>(rowptr, srcs, B.fs, B.fd, attn, out, n);
}

static void run_mlp(Bufs& B, const float* A, const float* Bx, const float* W,
                    const float* b, const float* g, const float* beta,
                    float* out, int n, float* stat)
{
    k_gemm_cat<<<ceil_div(n,64),128>>>(A, Bx, W, b, B.z, n, stat);
    k_bnapply<<<ceil_div(n*16,256),256>>>(B.z, stat, g, beta, out, n*16, 1.0f/n, 1);
}

extern "C" void kernel_launch(void* const* d_in, const int* in_sizes, int n_in,
                              void* d_out, int out_size)
{
    const float* emb      = (const float*)d_in[0];
    const float* bn0_g    = (const float*)d_in[1];
    const float* bn0_b    = (const float*)d_in[2];
    const float* gat_Wl   = (const float*)d_in[3];
    const float* gat_bl   = (const float*)d_in[4];
    const float* gat_Wr   = (const float*)d_in[5];
    const float* gat_br   = (const float*)d_in[6];
    const float* gat_attn = (const float*)d_in[7];
    const float* cheb_W   = (const float*)d_in[8];
    const float* cheb_b   = (const float*)d_in[9];
    const float* mlp_W    = (const float*)d_in[10];
    const float* mlp_b    = (const float*)d_in[11];
    const float* mlp_g    = (const float*)d_in[12];
    const float* mlp_beta = (const float*)d_in[13];
    const float* lam      = (const float*)d_in[14];
    const int* u2i_src = (const int*)d_in[15]; const int* u2i_dst = (const int*)d_in[16];
    const int* rc_src  = (const int*)d_in[17]; const int* rc_dst  = (const int*)d_in[18];
    const int* i2u_src = (const int*)d_in[19]; const int* i2u_dst = (const int*)d_in[20];
    const int* i2u_ids = (const int*)d_in[21];
    const int* sn_src  = (const int*)d_in[22]; const int* sn_dst  = (const int*)d_in[23];
    const int* snn_src = (const int*)d_in[24]; const int* snn_dst = (const int*)d_in[25];

    int ne_u2i = in_sizes[15], ne_rc = in_sizes[17], ne_i2u = in_sizes[19];
    int ne_sn  = in_sizes[22], ne_snn = in_sizes[24];

    float* out = (float*)d_out;
    Bufs B; get_bufs(B);

    int* rp_u2i = B.rowptr + 0*RPSZ; int* sc_u2i = B.srcs + 0;
    int* rp_rc  = B.rowptr + 1*RPSZ; int* sc_rc  = B.srcs + 1500000;
    int* rp_i2u = B.rowptr + 2*RPSZ; int* sc_i2u = B.srcs + 3000000;
    int* rp_sn  = B.rowptr + 3*RPSZ; int* sc_sn  = B.srcs + 4000000;
    int* rp_snn = B.rowptr + 4*RPSZ; int* sc_snn = B.srcs + 5000000;

    cudaMemsetAsync(B.stat, 0, 6*128*4);

    sort_graph(B, u2i_src, u2i_dst, ne_u2i, NUIN,   rp_u2i, sc_u2i, false);
    sort_graph(B, rc_src,  rc_dst,  ne_rc,  NUIN,   rp_rc,  sc_rc,  false);
    sort_graph(B, i2u_src, i2u_dst, ne_i2u, NPREDN, rp_i2u, sc_i2u, false);
    sort_graph(B, sn_src,  sn_dst,  ne_sn,  NPREDN, rp_sn,  sc_sn,  false);
    sort_graph(B, snn_src, snn_dst, ne_snn, NTOTN,  rp_snn, sc_snn, true);

    // 1. e = BN(emb); fused uie
    k_colstats<<<512,256>>>(emb, NNODESN, B.stat);
    k_bnapply_uie<<<ceil_div(NNODESN*16,256),256>>>(emb, B.stat, bn0_g, bn0_b,
                                                    B.ebn, B.uie, 1.0f/NNODESN);

    // 2. GAT0 (u2i), GAT1 (rc)
    run_gat(B, rp_u2i, sc_u2i, B.uie, nullptr, NUIN,
            gat_Wl+0*4096, gat_bl+0*64, gat_Wr+0*4096, gat_br+0*64, gat_attn+0*64, B.u2i);
    run_gat(B, rp_rc, sc_rc, B.u2i, nullptr, NUIN,
            gat_Wl+1*4096, gat_bl+1*64, gat_Wr+1*4096, gat_br+1*64, gat_attn+1*64, B.rc);

    // 3. GAT2 on su = uie[i2u_ids]
    run_gat(B, rp_i2u, sc_i2u, B.uie, i2u_ids, NPREDN,
            gat_Wl+2*4096, gat_bl+2*64, gat_Wr+2*4096, gat_br+2*64, gat_attn+2*64, B.i2u);

    // 4. soc
    k_copy4<<<ceil_div(NPREDN*16,256),256>>>(B.soc, B.uie, NPREDN*16);
    k_soc<<<ceil_div(NPREDN*16,256),256>>>(B.i2u, i2u_ids, B.soc, NPREDN);

    // 5. GAT3 (sn)
    run_gat(B, rp_sn, sc_sn, B.soc, nullptr, NPREDN,
            gat_Wl+3*4096, gat_bl+3*64, gat_Wr+3*4096, gat_br+3*64, gat_attn+3*64, B.sie);

    // 6. user_item_embed = mlp0([iie, sie])
    run_mlp(B, B.rc, B.sie, mlp_W+0*8192, mlp_b+0*64, mlp_g+0*64, mlp_beta+0*64,
            B.uitem, NPREDN, B.stat + 128);

    // 7. Cheb layer 1 (T0 = ebn[:TOTAL]); second lhat emits T2 = 2*lhat(T1)-T0
    k_lhat_node<<<ceil_div(NTOTN*16,256),256>>>(rp_snn, sc_snn, B.normv, B.ebn, lam,
                                                nullptr, B.T1, NTOTN);
    k_lhat_node<<<ceil_div(NTOTN*16,256),256>>>(rp_snn, sc_snn, B.normv, B.T1, lam,
                                                B.ebn, B.T2, NTOTN);
    k_gemm_cat3<<<ceil_div(NTOTN,64),128>>>(B.ebn, B.T1, B.T2, cheb_W, cheb_b, B.ch, NTOTN);

    // 8. Cheb layer 2
    k_lhat_node<<<ceil_div(NTOTN*16,256),256>>>(rp_snn, sc_snn, B.normv, B.ch, lam,
                                                nullptr, B.T1, NTOTN);
    k_lhat_node<<<ceil_div(NTOTN*16,256),256>>>(rp_snn, sc_snn, B.normv, B.T1, lam,
                                                B.ch, B.T2, NTOTN);
    k_gemm_cat3<<<ceil_div(NTOTN,64),128>>>(B.ch, B.T1, B.T2, cheb_W, cheb_b, B.ch2, NTOTN);

    // 9. GAT4 (snn)
    run_gat(B, rp_snn, sc_snn, B.ch2, nullptr, NTOTN,
            gat_Wl+4*4096, gat_bl+4*64, gat_Wr+4*4096, gat_br+4*64, gat_attn+4*64, B.gout);

    // 10. h_uP, h_uS
    run_mlp(B, B.uitem, B.ebn, mlp_W+1*8192, mlp_b+1*64, mlp_g+1*64, mlp_beta+1*64,
            B.huP, NPREDN, B.stat + 2*128);
    run_mlp(B, B.gout,  B.ebn, mlp_W+2*8192, mlp_b+2*64, mlp_g+2*64, mlp_beta+2*64,
            B.huS, NPREDN, B.stat + 3*128);

    // 11. fused gating + final MLPs
    k_softmul2<<<ceil_div(NPREDN*16,256),256>>>(B.huP, B.huS, B.mA, B.mA2, NPREDN);
    run_mlp(B, B.mA, B.huP, mlp_W+3*8192, mlp_b+3*64, mlp_g+3*64, mlp_beta+3*64,
            out, NPREDN, B.stat + 4*128);
    run_mlp(B, B.mA2, B.huS, mlp_W+4*8192, mlp_b+4*64, mlp_g+4*64, mlp_beta+4*64,
            out + (size_t)NPREDN*EMBD, NPREDN, B.stat + 5*128);
}

// round 16
// speedup vs baseline: 1.4135x; 1.0079x over previous
#include <cuda_runtime.h>
#include <math.h>

#define NPREDN 100000
#define NTOTN  120000
#define NUIN   200000
#define NNODESN 220000
#define EMBD 64
#define MAXE 1500000
#define RPSZ 200001
#define XSTRIDE 66   // transposed X tile row stride (floats): even -> 8B aligned pairs

typedef unsigned long long ull;

// ---------------- device scratch (static, no allocations) ----------------
__device__ float g_ebn[NNODESN*EMBD];
__device__ float g_uie[NUIN*EMBD];
__device__ float g_fs[NUIN*EMBD];
__device__ float g_fd[NUIN*EMBD];
__device__ float g_gout[NUIN*EMBD];
__device__ float g_u2i[NUIN*EMBD];
__device__ float g_rc[NUIN*EMBD];
__device__ float g_T1[NTOTN*EMBD];
__device__ float g_T2[NTOTN*EMBD];
__device__ float g_ch[NTOTN*EMBD];
__device__ float g_ch2[NTOTN*EMBD];
__device__ float g_i2u[NPREDN*EMBD];
__device__ float g_soc[NPREDN*EMBD];
__device__ float g_sie[NPREDN*EMBD];
__device__ float g_uitem[NPREDN*EMBD];
__device__ float g_huP[NPREDN*EMBD];
__device__ float g_huS[NPREDN*EMBD];
__device__ float g_mA[NPREDN*EMBD];
__device__ float g_mA2[NPREDN*EMBD];
__device__ float g_z[NPREDN*EMBD];
__device__ float g_stat[6*128];
// CSR sort scratch
__device__ int   g_srcs[7000000];
__device__ int   g_rowptr[5*RPSZ];
__device__ int   g_cnt[RPSZ];
__device__ int   g_pos[RPSZ];
__device__ int   g_part[256];
__device__ float g_deginv[NTOTN];
__device__ float g_normv[MAXE];

static inline int ceil_div(int a, int b) { return (a + b - 1) / b; }

__device__ __forceinline__ float lrelu(float v, float s) { return v > 0.f ? v : s*v; }

__device__ __forceinline__ ull dup_f(float x) {
    ull r; asm("mov.b64 %0, {%1,%1};" : "=l"(r) : "f"(x)); return r;
}
__device__ __forceinline__ float2 unpk(ull v) {
    float2 r; asm("mov.b64 {%0,%1}, %2;" : "=f"(r.x), "=f"(r.y) : "l"(v)); return r;
}
__device__ __forceinline__ void ffma2(ull& acc, ull a, ull b) {
    asm("fma.rn.f32x2 %0, %1, %2, %0;" : "+l"(acc) : "l"(a), "l"(b));
}

// ====== GEMM family: 64-row blocks, 128 threads, 8 rows x 4 cols per thread =======
__device__ __forceinline__ void load_x64_t(const float* __restrict__ X,
                                           const int* __restrict__ ids,
                                           float* Xt, int row0, int n, int tid)
{
    #pragma unroll
    for (int i = 0; i < 8; i++) {
        int idx = tid + i*128;
        int r = idx >> 4, c4 = idx & 15;
        int gr = row0 + r;
        float4 v = make_float4(0.f,0.f,0.f,0.f);
        if (gr < n) {
            int sr = ids ? ids[gr] : gr;
            v = ((const float4*)X)[(size_t)sr*16 + c4];
        }
        int k0 = c4*4;
        Xt[(k0+0)*XSTRIDE + r] = v.x;
        Xt[(k0+1)*XSTRIDE + r] = v.y;
        Xt[(k0+2)*XSTRIDE + r] = v.z;
        Xt[(k0+3)*XSTRIDE + r] = v.w;
    }
}
__device__ __forceinline__ void load_w64(const float* __restrict__ W, float* Ws, int tid)
{
    #pragma unroll
    for (int i = 0; i < 8; i++)
        ((float4*)Ws)[tid + i*128] = ((const float4*)W)[tid + i*128];
}

__device__ __forceinline__ void mm_f2t(const float* Xt, const float* Ws,
                                       ull acc[4][4], int tx, int ty)
{
    #pragma unroll 8
    for (int k = 0; k < 64; k++) {
        float4 b = *(const float4*)&Ws[k*64 + tx*4];
        ull b0 = dup_f(b.x), b1 = dup_f(b.y), b2 = dup_f(b.z), b3 = dup_f(b.w);
        const ull* ap = (const ull*)&Xt[k*XSTRIDE + ty*8];
        #pragma unroll
        for (int i = 0; i < 4; i++) {
            ull a = ap[i];
            ffma2(acc[i][0], a, b0);
            ffma2(acc[i][1], a, b1);
            ffma2(acc[i][2], a, b2);
            ffma2(acc[i][3], a, b3);
        }
    }
}

__device__ __forceinline__ void unpack_acc(ull acc[4][4], float f[8][4])
{
    #pragma unroll
    for (int i = 0; i < 4; i++) {
        #pragma unroll
        for (int j = 0; j < 4; j++) {
            float2 p = unpk(acc[i][j]);
            f[2*i][j]   = p.x;
            f[2*i+1][j] = p.y;
        }
    }
}

__device__ __forceinline__ void store8x4(float* __restrict__ Y, float f[8][4],
                                         const float* __restrict__ bias,
                                         int row0, int n, int tx, int ty, int act)
{
    float4 bb = bias ? ((const float4*)bias)[tx] : make_float4(0.f,0.f,0.f,0.f);
    #pragma unroll
    for (int i = 0; i < 8; i++) {
        int gr = row0 + ty*8 + i;
        if (gr < n) {
            float4 v = make_float4(f[i][0]+bb.x, f[i][1]+bb.y, f[i][2]+bb.z, f[i][3]+bb.w);
            if (act) { v.x=lrelu(v.x,0.01f); v.y=lrelu(v.y,0.01f);
                       v.z=lrelu(v.z,0.01f); v.w=lrelu(v.w,0.01f); }
            ((float4*)Y)[(size_t)gr*16 + tx] = v;
        }
    }
}

__device__ __forceinline__ void stats_epilogue(float f[8][4], float* sh,
                                               const float* __restrict__ bias,
                                               float* __restrict__ stat,
                                               int row0, int n, int tx, int ty, int tid)
{
    float4 bb = bias ? ((const float4*)bias)[tx] : make_float4(0.f,0.f,0.f,0.f);
    float s[4] = {0,0,0,0}, q[4] = {0,0,0,0};
    #pragma unroll
    for (int i = 0; i < 8; i++) {
        int gr = row0 + ty*8 + i;
        if (gr < n) {
            float v0 = f[i][0]+bb.x, v1 = f[i][1]+bb.y;
            float v2 = f[i][2]+bb.z, v3 = f[i][3]+bb.w;
            s[0]+=v0; s[1]+=v1; s[2]+=v2; s[3]+=v3;
            q[0]+=v0*v0; q[1]+=v1*v1; q[2]+=v2*v2; q[3]+=v3*v3;
        }
    }
    __syncthreads();
    #pragma unroll
    for (int k = 0; k < 4; k++) {
        sh[ty*128 + tx*8 + k]     = s[k];
        sh[ty*128 + tx*8 + 4 + k] = q[k];
    }
    __syncthreads();
    if (tid < 128) {
        float t = 0.f;
        #pragma unroll
        for (int w = 0; w < 8; w++) t += sh[w*128 + tid];
        int txx = tid >> 3, qq = tid & 7;
        int col = txx*4 + (qq & 3);
        atomicAdd(&stat[(qq < 4 ? col : 64 + col)], t);
    }
}

__global__ void __launch_bounds__(128) k_gemm_dual(
    const float* __restrict__ X, const int* __restrict__ ids,
    const float* __restrict__ W1, const float* __restrict__ b1, float* __restrict__ Y1,
    const float* __restrict__ W2, const float* __restrict__ b2, float* __restrict__ Y2,
    int n)
{
    __shared__ float Xt[64*XSTRIDE];
    __shared__ float Ws[4096];
    int tid = threadIdx.x, tx = tid & 15, ty = tid >> 4;
    int row0 = blockIdx.x * 64;
    load_x64_t(X, ids, Xt, row0, n, tid);
    load_w64(W1, Ws, tid);
    __syncthreads();
    {
        ull acc[4][4] = {};
        mm_f2t(Xt, Ws, acc, tx, ty);
        float f[8][4]; unpack_acc(acc, f);
        store8x4(Y1, f, b1, row0, n, tx, ty, 0);
    }
    __syncthreads();
    load_w64(W2, Ws, tid);
    __syncthreads();
    {
        ull acc[4][4] = {};
        mm_f2t(Xt, Ws, acc, tx, ty);
        float f[8][4]; unpack_acc(acc, f);
        store8x4(Y2, f, b2, row0, n, tx, ty, 0);
    }
}

__global__ void __launch_bounds__(128) k_gemm_cat(
    const float* __restrict__ A, const float* __restrict__ Bx,
    const float* __restrict__ W, const float* __restrict__ bias,
    float* __restrict__ Y, int n, float* __restrict__ stat)
{
    __shared__ float Xt[64*XSTRIDE];
    __shared__ float Ws[4096];
    int tid = threadIdx.x, tx = tid & 15, ty = tid >> 4;
    int row0 = blockIdx.x * 64;
    ull acc[4][4] = {};
    load_x64_t(A, nullptr, Xt, row0, n, tid);
    load_w64(W, Ws, tid);
    __syncthreads();
    mm_f2t(Xt, Ws, acc, tx, ty);
    __syncthreads();
    load_x64_t(Bx, nullptr, Xt, row0, n, tid);
    load_w64(W + 4096, Ws, tid);
    __syncthreads();
    mm_f2t(Xt, Ws, acc, tx, ty);
    float f[8][4]; unpack_acc(acc, f);
    store8x4(Y, f, bias, row0, n, tx, ty, 0);
    if (stat) stats_epilogue(f, Ws, bias, stat, row0, n, tx, ty, tid);
}

// cheb: Y = lrelu(X0@W0 + X1@W1 + X2c@W2 + bias); X2c pre-combined (2*lhat(T1)-T0)
__global__ void __launch_bounds__(128) k_gemm_cat3(
    const float* __restrict__ X0, const float* __restrict__ X1, const float* __restrict__ X2c,
    const float* __restrict__ W, const float* __restrict__ bias,
    float* __restrict__ Y, int n)
{
    __shared__ float Xt[64*XSTRIDE];
    __shared__ float Ws[4096];
    int tid = threadIdx.x, tx = tid & 15, ty = tid >> 4;
    int row0 = blockIdx.x * 64;
    ull acc[4][4] = {};
    load_x64_t(X0, nullptr, Xt, row0, n, tid);
    load_w64(W, Ws, tid);
    __syncthreads();
    mm_f2t(Xt, Ws, acc, tx, ty);
    __syncthreads();
    load_x64_t(X1, nullptr, Xt, row0, n, tid);
    load_w64(W + 4096, Ws, tid);
    __syncthreads();
    mm_f2t(Xt, Ws, acc, tx, ty);
    __syncthreads();
    load_x64_t(X2c, nullptr, Xt, row0, n, tid);
    load_w64(W + 8192, Ws, tid);
    __syncthreads();
    mm_f2t(Xt, Ws, acc, tx, ty);
    float f[8][4]; unpack_acc(acc, f);
    store8x4(Y, f, bias, row0, n, tx, ty, 1);
}

// ---------------- BN ----------------
__global__ void k_colstats(const float* __restrict__ X, int n, float* __restrict__ stat)
{
    int c  = threadIdx.x & 63;
    int tg = threadIdx.x >> 6;
    float s = 0.f, sq = 0.f;
    for (int r = blockIdx.x*4 + tg; r < n; r += gridDim.x*4) {
        float v = X[(size_t)r*64 + c];
        s += v; sq += v*v;
    }
    __shared__ float sh[4][128];
    sh[tg][c] = s; sh[tg][64+c] = sq;
    __syncthreads();
    if (tg == 0) {
        float ts = sh[0][c]+sh[1][c]+sh[2][c]+sh[3][c];
        float tq = sh[0][64+c]+sh[1][64+c]+sh[2][64+c]+sh[3][64+c];
        atomicAdd(&stat[c], ts);
        atomicAdd(&stat[64+c], tq);
    }
}

__device__ __forceinline__ float4 bn4(float4 x, float4 s1, float4 s2,
                                      float4 gg, float4 bb, float invn)
{
    float4 o;
    float mu = s1.x*invn, var = s2.x*invn - mu*mu;
    o.x = (x.x-mu)*rsqrtf(var+1e-5f)*gg.x + bb.x;
    mu = s1.y*invn; var = s2.y*invn - mu*mu;
    o.y = (x.y-mu)*rsqrtf(var+1e-5f)*gg.y + bb.y;
    mu = s1.z*invn; var = s2.z*invn - mu*mu;
    o.z = (x.z-mu)*rsqrtf(var+1e-5f)*gg.z + bb.z;
    mu = s1.w*invn; var = s2.w*invn - mu*mu;
    o.w = (x.w-mu)*rsqrtf(var+1e-5f)*gg.w + bb.w;
    return o;
}

__global__ void k_bnapply(const float* __restrict__ X, const float* __restrict__ stat,
                          const float* __restrict__ g, const float* __restrict__ b,
                          float* __restrict__ Y, int nq, float invn, int act)
{
    int i = blockIdx.x*blockDim.x + threadIdx.x;
    if (i >= nq) return;
    int c4 = i & 15;
    float4 o = bn4(((const float4*)X)[i], ((const float4*)stat)[c4],
                   ((const float4*)stat)[16+c4], ((const float4*)g)[c4],
                   ((const float4*)b)[c4], invn);
    if (act) { o.x=lrelu(o.x,0.01f); o.y=lrelu(o.y,0.01f);
               o.z=lrelu(o.z,0.01f); o.w=lrelu(o.w,0.01f); }
    ((float4*)Y)[i] = o;
}

__global__ void k_bnapply_uie(const float* __restrict__ X, const float* __restrict__ stat,
                              const float* __restrict__ g, const float* __restrict__ b,
                              float* __restrict__ ebn, float* __restrict__ uie, float invn)
{
    int i = blockIdx.x*blockDim.x + threadIdx.x;
    if (i >= NNODESN*16) return;
    int c4 = i & 15;
    float4 o = bn4(((const float4*)X)[i], ((const float4*)stat)[c4],
                   ((const float4*)stat)[16+c4], ((const float4*)g)[c4],
                   ((const float4*)b)[c4], invn);
    ((float4*)ebn)[i] = o;
    int row = i >> 4;
    if (row < NPREDN) ((float4*)uie)[i] = o;
    else if (row >= NNODESN - 100000)
        ((float4*)uie)[(size_t)(row - (NNODESN - NUIN))*16 + c4] = o;
}

// ================= counting sort by dst (CSR build) =================
__global__ void k_hist(const int* __restrict__ dst, int ne, int* __restrict__ cnt)
{
    int i = blockIdx.x*blockDim.x + threadIdx.x;
    if (i < ne) atomicAdd(&cnt[dst[i]], 1);
}
__global__ void k_scan_part(const int* __restrict__ cnt, int n, int* __restrict__ part)
{
    __shared__ int sh[256];
    int t = threadIdx.x, base = blockIdx.x*1024 + t*4;
    int s = 0;
    #pragma unroll
    for (int j = 0; j < 4; j++) { int i = base+j; if (i < n) s += cnt[i]; }
    sh[t] = s; __syncthreads();
    #pragma unroll
    for (int off = 128; off; off >>= 1) {
        if (t < off) sh[t] += sh[t+off];
        __syncthreads();
    }
    if (!t) part[blockIdx.x] = sh[0];
}
__global__ void k_scan_top(int* __restrict__ part, int nb, int* __restrict__ totptr)
{
    __shared__ int sh[256];
    int t = threadIdx.x;
    int v = t < nb ? part[t] : 0;
    sh[t] = v; __syncthreads();
    for (int off = 1; off < 256; off <<= 1) {
        int u = t >= off ? sh[t-off] : 0;
        __syncthreads();
        sh[t] += u;
        __syncthreads();
    }
    int excl = t ? sh[t-1] : 0;
    if (t < nb) part[t] = excl;
    if (t == 255) *totptr = sh[255];
}
__global__ void k_scan_final(const int* __restrict__ cnt, const int* __restrict__ part, int n,
                             int* __restrict__ rowptr, int* __restrict__ pos)
{
    __shared__ int sh[256];
    int t = threadIdx.x, base = blockIdx.x*1024 + t*4;
    int c[4]; int s = 0;
    #pragma unroll
    for (int j = 0; j < 4; j++) { int i = base+j; c[j] = (i < n) ? cnt[i] : 0; s += c[j]; }
    sh[t] = s; __syncthreads();
    for (int off = 1; off < 256; off <<= 1) {
        int u = t >= off ? sh[t-off] : 0;
        __syncthreads();
        sh[t] += u;
        __syncthreads();
    }
    int run = (t ? sh[t-1] : 0) + part[blockIdx.x];
    #pragma unroll
    for (int j = 0; j < 4; j++) {
        int i = base+j;
        if (i < n) { rowptr[i] = run; pos[i] = run; }
        run += c[j];
    }
}
__global__ void k_scatter(const int* __restrict__ src, const int* __restrict__ dst, int ne,
                          int* __restrict__ pos, int* __restrict__ srcs)
{
    int i = blockIdx.x*blockDim.x + threadIdx.x;
    if (i >= ne) return;
    int p = atomicAdd(&pos[dst[i]], 1);
    srcs[p] = src[i];
}
__global__ void k_deginv(const int* __restrict__ rowptr, float* __restrict__ dinv, int n)
{
    int i = blockIdx.x*blockDim.x + threadIdx.x;
    if (i < n) dinv[i] = rsqrtf(fmaxf((float)(rowptr[i+1]-rowptr[i]), 1.f));
}
__global__ void k_scatter_norm(const int* __restrict__ src, const int* __restrict__ dst, int ne,
                               int* __restrict__ pos, const float* __restrict__ dinv,
                               int* __restrict__ srcs, float* __restrict__ normv)
{
    int i = blockIdx.x*blockDim.x + threadIdx.x;
    if (i >= ne) return;
    int s = src[i], d = dst[i];
    int p = atomicAdd(&pos[d], 1);
    srcs[p] = s;
    normv[p] = dinv[s]*dinv[d];
}

// ========== node-parallel GAT aggregation (16 lanes per dst node, 4-edge MLP) ==========
__global__ void k_gat_node(const int* __restrict__ rowptr, const int* __restrict__ srcs,
                           const float* __restrict__ fs, const float* __restrict__ fd,
                           const float* __restrict__ attn, float* __restrict__ out, int n)
{
    int w = (blockIdx.x*blockDim.x + threadIdx.x) >> 4;
    int l = threadIdx.x & 15;
    unsigned mask = 0xFFFFu << (threadIdx.x & 16);
    if (w >= n) return;
    int beg = rowptr[w], end = rowptr[w+1];
    float4 fdv = ((const float4*)fd)[(size_t)w*16 + l];
    float4 at  = ((const float4*)attn)[l];
    float4 acc = make_float4(0.f,0.f,0.f,0.f);
    float den = 0.f;
    int e = beg;
    for (; e+4 <= end; e += 4) {
        int s0 = srcs[e], s1 = srcs[e+1], s2 = srcs[e+2], s3 = srcs[e+3];
        float4 f0 = ((const float4*)fs)[(size_t)s0*16 + l];
        float4 f1 = ((const float4*)fs)[(size_t)s1*16 + l];
        float4 f2 = ((const float4*)fs)[(size_t)s2*16 + l];
        float4 f3 = ((const float4*)fs)[(size_t)s3*16 + l];
        float t0 = lrelu(f0.x+fdv.x,0.2f)*at.x + lrelu(f0.y+fdv.y,0.2f)*at.y
                 + lrelu(f0.z+fdv.z,0.2f)*at.z + lrelu(f0.w+fdv.w,0.2f)*at.w;
        float t1 = lrelu(f1.x+fdv.x,0.2f)*at.x + lrelu(f1.y+fdv.y,0.2f)*at.y
                 + lrelu(f1.z+fdv.z,0.2f)*at.z + lrelu(f1.w+fdv.w,0.2f)*at.w;
        float t2 = lrelu(f2.x+fdv.x,0.2f)*at.x + lrelu(f2.y+fdv.y,0.2f)*at.y
                 + lrelu(f2.z+fdv.z,0.2f)*at.z + lrelu(f2.w+fdv.w,0.2f)*at.w;
        float t3 = lrelu(f3.x+fdv.x,0.2f)*at.x + lrelu(f3.y+fdv.y,0.2f)*at.y
                 + lrelu(f3.z+fdv.z,0.2f)*at.z + lrelu(f3.w+fdv.w,0.2f)*at.w;
        #pragma unroll
        for (int o = 8; o; o >>= 1) {
            t0 += __shfl_xor_sync(mask, t0, o, 16);
            t1 += __shfl_xor_sync(mask, t1, o, 16);
            t2 += __shfl_xor_sync(mask, t2, o, 16);
            t3 += __shfl_xor_sync(mask, t3, o, 16);
        }
        float e0 = __expf(t0), e1 = __expf(t1), e2 = __expf(t2), e3 = __expf(t3);
        den += (e0 + e1) + (e2 + e3);
        acc.x += e0*f0.x + e1*f1.x + e2*f2.x + e3*f3.x;
        acc.y += e0*f0.y + e1*f1.y + e2*f2.y + e3*f3.y;
        acc.z += e0*f0.z + e1*f1.z + e2*f2.z + e3*f3.z;
        acc.w += e0*f0.w + e1*f1.w + e2*f2.w + e3*f3.w;
    }
    for (; e < end; e++) {
        int s0 = srcs[e];
        float4 f0 = ((const float4*)fs)[(size_t)s0*16 + l];
        float t0 = lrelu(f0.x+fdv.x,0.2f)*at.x + lrelu(f0.y+fdv.y,0.2f)*at.y
                 + lrelu(f0.z+fdv.z,0.2f)*at.z + lrelu(f0.w+fdv.w,0.2f)*at.w;
        #pragma unroll
        for (int o = 8; o; o >>= 1) t0 += __shfl_xor_sync(mask, t0, o, 16);
        float e0 = __expf(t0);
        den += e0;
        acc.x += e0*f0.x; acc.y += e0*f0.y; acc.z += e0*f0.z; acc.w += e0*f0.w;
    }
    float inv = den > 0.f ? 1.f/den : 0.f;
    ((float4*)out)[(size_t)w*16 + l] =
        make_float4(lrelu(acc.x*inv,0.01f), lrelu(acc.y*inv,0.01f),
                    lrelu(acc.z*inv,0.01f), lrelu(acc.w*inv,0.01f));
}

// node-parallel lhat (16 lanes/node, 4-edge MLP)
__global__ void k_lhat_node(const int* __restrict__ rowptr, const int* __restrict__ srcs,
                            const float* __restrict__ normv, const float* __restrict__ v,
                            const float* __restrict__ lamp, const float* __restrict__ t0arr,
                            float* __restrict__ out, int n)
{
    int w = (blockIdx.x*blockDim.x + threadIdx.x) >> 4;
    int l = threadIdx.x & 15;
    if (w >= n) return;
    int beg = rowptr[w], end = rowptr[w+1];
    float4 acc = make_float4(0.f,0.f,0.f,0.f);
    int e = beg;
    for (; e+4 <= end; e += 4) {
        int s0 = srcs[e], s1 = srcs[e+1], s2 = srcs[e+2], s3 = srcs[e+3];
        float n0 = normv[e], n1 = normv[e+1], n2 = normv[e+2], n3 = normv[e+3];
        float4 f0 = ((const float4*)v)[(size_t)s0*16 + l];
        float4 f1 = ((const float4*)v)[(size_t)s1*16 + l];
        float4 f2 = ((const float4*)v)[(size_t)s2*16 + l];
        float4 f3 = ((const float4*)v)[(size_t)s3*16 + l];
        acc.x += (n0*f0.x + n1*f1.x) + (n2*f2.x + n3*f3.x);
        acc.y += (n0*f0.y + n1*f1.y) + (n2*f2.y + n3*f3.y);
        acc.z += (n0*f0.z + n1*f1.z) + (n2*f2.z + n3*f3.z);
        acc.w += (n0*f0.w + n1*f1.w) + (n2*f2.w + n3*f3.w);
    }
    for (; e < end; e++) {
        int s0 = srcs[e];
        float n0 = normv[e];
        float4 f0 = ((const float4*)v)[(size_t)s0*16 + l];
        acc.x += n0*f0.x; acc.y += n0*f0.y; acc.z += n0*f0.z; acc.w += n0*f0.w;
    }
    float c = 2.f / __ldg(lamp);
    float4 vv = ((const float4*)v)[(size_t)w*16 + l];
    float4 o = make_float4(c*(vv.x-acc.x)-vv.x, c*(vv.y-acc.y)-vv.y,
                           c*(vv.z-acc.z)-vv.z, c*(vv.w-acc.w)-vv.w);
    if (t0arr) {
        float4 t0 = ((const float4*)t0arr)[(size_t)w*16 + l];
        o = make_float4(2.f*o.x-t0.x, 2.f*o.y-t0.y, 2.f*o.z-t0.z, 2.f*o.w-t0.w);
    }
    ((float4*)out)[(size_t)w*16 + l] = o;
}

// ---------------- misc ----------------
// fused soc build: soc[ids[r]] = (sum(i2u[r]) != 0) ? i2u[r] : uie[ids[r]]
__global__ void k_socmerge(const float* __restrict__ i2u, const float* __restrict__ uie,
                           const int* __restrict__ ids, float* __restrict__ soc, int n)
{
    int t = blockIdx.x*blockDim.x + threadIdx.x;
    int r = t >> 4, l = t & 15;
    if (r >= n) return;
    float4 v = ((const float4*)i2u)[(size_t)r*16 + l];
    float s = v.x + v.y + v.z + v.w;
    unsigned mask = 0xFFFFu << (threadIdx.x & 16);
    #pragma unroll
    for (int o = 8; o; o >>= 1) s += __shfl_xor_sync(mask, s, o, 16);
    int tr = ids[r];
    float4 u = ((const float4*)uie)[(size_t)tr*16 + l];
    ((float4*)soc)[(size_t)tr*16 + l] = (s != 0.f) ? v : u;
}
__global__ void k_softmul2(const float* __restrict__ hP, const float* __restrict__ hS,
                           float* __restrict__ mAP, float* __restrict__ mAS, int n)
{
    int t = blockIdx.x*blockDim.x + threadIdx.x;
    int r = t >> 4, l = t & 15;
    unsigned mask = 0xFFFFu << (threadIdx.x & 16);
    if (r >= n) return;
    size_t base = (size_t)r*16 + l;
    float4 p = ((const float4*)hP)[base];
    float4 s = ((const float4*)hS)[base];
    float mp = fmaxf(fmaxf(p.x,p.y), fmaxf(p.z,p.w));
    float ms = fmaxf(fmaxf(s.x,s.y), fmaxf(s.z,s.w));
    #pragma unroll
    for (int o = 8; o; o >>= 1) {
        mp = fmaxf(mp, __shfl_xor_sync(mask, mp, o, 16));
        ms = fmaxf(ms, __shfl_xor_sync(mask, ms, o, 16));
    }
    float4 eP = make_float4(__expf(p.x-mp), __expf(p.y-mp), __expf(p.z-mp), __expf(p.w-mp));
    float4 eS = make_float4(__expf(s.x-ms), __expf(s.y-ms), __expf(s.z-ms), __expf(s.w-ms));
    float sp = eP.x+eP.y+eP.z+eP.w;
    float ss = eS.x+eS.y+eS.z+eS.w;
    #pragma unroll
    for (int o = 8; o; o >>= 1) {
        sp += __shfl_xor_sync(mask, sp, o, 16);
        ss += __shfl_xor_sync(mask, ss, o, 16);
    }
    float ip = 1.f/sp, is = 1.f/ss;
    float4 hm = make_float4(p.x*s.x, p.y*s.y, p.z*s.z, p.w*s.w);
    ((float4*)mAP)[base] = make_float4(hm.x*eP.x*ip, hm.y*eP.y*ip, hm.z*eP.z*ip, hm.w*eP.w*ip);
    ((float4*)mAS)[base] = make_float4(hm.x*eS.x*is, hm.y*eS.y*is, hm.z*eS.z*is, hm.w*eS.w*is);
}

// ---------------- host-side composition ----------------
struct Bufs {
    float *ebn,*uie,*fs,*fd,*gout,*u2i,*rc,*T1,*T2,*ch,*ch2,*i2u,*soc,*sie,
          *uitem,*huP,*huS,*mA,*mA2,*z,*stat,*deginv,*normv;
    int *srcs,*rowptr,*cnt,*pos,*part;
};
static void get_bufs(Bufs& B) {
    cudaGetSymbolAddress((void**)&B.ebn,  g_ebn);
    cudaGetSymbolAddress((void**)&B.uie,  g_uie);
    cudaGetSymbolAddress((void**)&B.fs,   g_fs);
    cudaGetSymbolAddress((void**)&B.fd,   g_fd);
    cudaGetSymbolAddress((void**)&B.gout, g_gout);
    cudaGetSymbolAddress((void**)&B.u2i,  g_u2i);
    cudaGetSymbolAddress((void**)&B.rc,   g_rc);
    cudaGetSymbolAddress((void**)&B.T1,   g_T1);
    cudaGetSymbolAddress((void**)&B.T2,   g_T2);
    cudaGetSymbolAddress((void**)&B.ch,   g_ch);
    cudaGetSymbolAddress((void**)&B.ch2,  g_ch2);
    cudaGetSymbolAddress((void**)&B.i2u,  g_i2u);
    cudaGetSymbolAddress((void**)&B.soc,  g_soc);
    cudaGetSymbolAddress((void**)&B.sie,  g_sie);
    cudaGetSymbolAddress((void**)&B.uitem,g_uitem);
    cudaGetSymbolAddress((void**)&B.huP,  g_huP);
    cudaGetSymbolAddress((void**)&B.huS,  g_huS);
    cudaGetSymbolAddress((void**)&B.mA,   g_mA);
    cudaGetSymbolAddress((void**)&B.mA2,  g_mA2);
    cudaGetSymbolAddress((void**)&B.z,    g_z);
    cudaGetSymbolAddress((void**)&B.stat, g_stat);
    cudaGetSymbolAddress((void**)&B.deginv, g_deginv);
    cudaGetSymbolAddress((void**)&B.normv,  g_normv);
    cudaGetSymbolAddress((void**)&B.srcs,   g_srcs);
    cudaGetSymbolAddress((void**)&B.rowptr, g_rowptr);
    cudaGetSymbolAddress((void**)&B.cnt,    g_cnt);
    cudaGetSymbolAddress((void**)&B.pos,    g_pos);
    cudaGetSymbolAddress((void**)&B.part,   g_part);
}

static void sort_graph(Bufs& B, const int* src, const int* dst, int ne, int n,
                       int* rowptr, int* srcs, bool with_norm)
{
    cudaMemsetAsync(B.cnt, 0, (size_t)n*4);
    k_hist<<<ceil_div(ne,256),256>>>(dst, ne, B.cnt);
    int nb = ceil_div(n, 1024);
    k_scan_part<<<nb,256>>>(B.cnt, n, B.part);
    k_scan_top<<<1,256>>>(B.part, nb, rowptr + n);
    k_scan_final<<<nb,256>>>(B.cnt, B.part, n, rowptr, B.pos);
    if (with_norm) {
        k_deginv<<<ceil_div(n,256),256>>>(rowptr, B.deginv, n);
        k_scatter_norm<<<ceil_div(ne,256),256>>>(src, dst, ne, B.pos, B.deginv,
                                                 srcs, B.normv);
    } else {
        k_scatter<<<ceil_div(ne,256),256>>>(src, dst, ne, B.pos, srcs);
    }
}

static void run_gat(Bufs& B, const int* rowptr, const int* srcs,
                    const float* x, const int* ids, int n,
                    const float* Wl, const float* bl,
                    const float* Wr, const float* br,
                    const float* attn, float* out)
{
    k_gemm_dual<<<ceil_div(n,64),128>>>(x, ids, Wl, bl, B.fs, Wr, br, B.fd, n);
    k_gat_node<<<ceil_div(n*16,256),256>>>(rowptr, srcs, B.fs, B.fd, attn, out, n);
}

static void run_mlp(Bufs& B, const float* A, const float* Bx, const float* W,
                    const float* b, const float* g, const float* beta,
                    float* out, int n, float* stat)
{
    k_gemm_cat<<<ceil_div(n,64),128>>>(A, Bx, W, b, B.z, n, stat);
    k_bnapply<<<ceil_div(n*16,256),256>>>(B.z, stat, g, beta, out, n*16, 1.0f/n, 1);
}

extern "C" void kernel_launch(void* const* d_in, const int* in_sizes, int n_in,
                              void* d_out, int out_size)
{
    const float* emb      = (const float*)d_in[0];
    const float* bn0_g    = (const float*)d_in[1];
    const float* bn0_b    = (const float*)d_in[2];
    const float* gat_Wl   = (const float*)d_in[3];
    const float* gat_bl   = (const float*)d_in[4];
    const float* gat_Wr   = (const float*)d_in[5];
    const float* gat_br   = (const float*)d_in[6];
    const float* gat_attn = (const float*)d_in[7];
    const float* cheb_W   = (const float*)d_in[8];
    const float* cheb_b   = (const float*)d_in[9];
    const float* mlp_W    = (const float*)d_in[10];
    const float* mlp_b    = (const float*)d_in[11];
    const float* mlp_g    = (const float*)d_in[12];
    const float* mlp_beta = (const float*)d_in[13];
    const float* lam      = (const float*)d_in[14];
    const int* u2i_src = (const int*)d_in[15]; const int* u2i_dst = (const int*)d_in[16];
    const int* rc_src  = (const int*)d_in[17]; const int* rc_dst  = (const int*)d_in[18];
    const int* i2u_src = (const int*)d_in[19]; const int* i2u_dst = (const int*)d_in[20];
    const int* i2u_ids = (const int*)d_in[21];
    const int* sn_src  = (const int*)d_in[22]; const int* sn_dst  = (const int*)d_in[23];
    const int* snn_src = (const int*)d_in[24]; const int* snn_dst = (const int*)d_in[25];

    int ne_u2i = in_sizes[15], ne_rc = in_sizes[17], ne_i2u = in_sizes[19];
    int ne_sn  = in_sizes[22], ne_snn = in_sizes[24];

    float* out = (float*)d_out;
    Bufs B; get_bufs(B);

    int* rp_u2i = B.rowptr + 0*RPSZ; int* sc_u2i = B.srcs + 0;
    int* rp_rc  = B.rowptr + 1*RPSZ; int* sc_rc  = B.srcs + 1500000;
    int* rp_i2u = B.rowptr + 2*RPSZ; int* sc_i2u = B.srcs + 3000000;
    int* rp_sn  = B.rowptr + 3*RPSZ; int* sc_sn  = B.srcs + 4000000;
    int* rp_snn = B.rowptr + 4*RPSZ; int* sc_snn = B.srcs + 5000000;

    cudaMemsetAsync(B.stat, 0, 6*128*4);

    sort_graph(B, u2i_src, u2i_dst, ne_u2i, NUIN,   rp_u2i, sc_u2i, false);
    sort_graph(B, rc_src,  rc_dst,  ne_rc,  NUIN,   rp_rc,  sc_rc,  false);
    sort_graph(B, i2u_src, i2u_dst, ne_i2u, NPREDN, rp_i2u, sc_i2u, false);
    sort_graph(B, sn_src,  sn_dst,  ne_sn,  NPREDN, rp_sn,  sc_sn,  false);
    sort_graph(B, snn_src, snn_dst, ne_snn, NTOTN,  rp_snn, sc_snn, true);

    // 1. e = BN(emb); fused uie
    k_colstats<<<512,256>>>(emb, NNODESN, B.stat);
    k_bnapply_uie<<<ceil_div(NNODESN*16,256),256>>>(emb, B.stat, bn0_g, bn0_b,
                                                    B.ebn, B.uie, 1.0f/NNODESN);

    // 2. GAT0 (u2i), GAT1 (rc)
    run_gat(B, rp_u2i, sc_u2i, B.uie, nullptr, NUIN,
            gat_Wl+0*4096, gat_bl+0*64, gat_Wr+0*4096, gat_br+0*64, gat_attn+0*64, B.u2i);
    run_gat(B, rp_rc, sc_rc, B.u2i, nullptr, NUIN,
            gat_Wl+1*4096, gat_bl+1*64, gat_Wr+1*4096, gat_br+1*64, gat_attn+1*64, B.rc);

    // 3. GAT2 on su = uie[i2u_ids]
    run_gat(B, rp_i2u, sc_i2u, B.uie, i2u_ids, NPREDN,
            gat_Wl+2*4096, gat_bl+2*64, gat_Wr+2*4096, gat_br+2*64, gat_attn+2*64, B.i2u);

    // 4. soc (fused copy + mask-merge, one pass)
    k_socmerge<<<ceil_div(NPREDN*16,256),256>>>(B.i2u, B.uie, i2u_ids, B.soc, NPREDN);

    // 5. GAT3 (sn)
    run_gat(B, rp_sn, sc_sn, B.soc, nullptr, NPREDN,
            gat_Wl+3*4096, gat_bl+3*64, gat_Wr+3*4096, gat_br+3*64, gat_attn+3*64, B.sie);

    // 6. user_item_embed = mlp0([iie, sie])
    run_mlp(B, B.rc, B.sie, mlp_W+0*8192, mlp_b+0*64, mlp_g+0*64, mlp_beta+0*64,
            B.uitem, NPREDN, B.stat + 128);

    // 7. Cheb layer 1 (T0 = ebn[:TOTAL]); second lhat emits T2 = 2*lhat(T1)-T0
    k_lhat_node<<<ceil_div(NTOTN*16,256),256>>>(rp_snn, sc_snn, B.normv, B.ebn, lam,
                                                nullptr, B.T1, NTOTN);
    k_lhat_node<<<ceil_div(NTOTN*16,256),256>>>(rp_snn, sc_snn, B.normv, B.T1, lam,
                                                B.ebn, B.T2, NTOTN);
    k_gemm_cat3<<<ceil_div(NTOTN,64),128>>>(B.ebn, B.T1, B.T2, cheb_W, cheb_b, B.ch, NTOTN);

    // 8. Cheb layer 2
    k_lhat_node<<<ceil_div(NTOTN*16,256),256>>>(rp_snn, sc_snn, B.normv, B.ch, lam,
                                                nullptr, B.T1, NTOTN);
    k_lhat_node<<<ceil_div(NTOTN*16,256),256>>>(rp_snn, sc_snn, B.normv, B.T1, lam,
                                                B.ch, B.T2, NTOTN);
    k_gemm_cat3<<<ceil_div(NTOTN,64),128>>>(B.ch, B.T1, B.T2, cheb_W, cheb_b, B.ch2, NTOTN);

    // 9. GAT4 (snn)
    run_gat(B, rp_snn, sc_snn, B.ch2, nullptr, NTOTN,
            gat_Wl+4*4096, gat_bl+4*64, gat_Wr+4*4096, gat_br+4*64, gat_attn+4*64, B.gout);

    // 10. h_uP, h_uS
    run_mlp(B, B.uitem, B.ebn, mlp_W+1*8192, mlp_b+1*64, mlp_g+1*64, mlp_beta+1*64,
            B.huP, NPREDN, B.stat + 2*128);
    run_mlp(B, B.gout,  B.ebn, mlp_W+2*8192, mlp_b+2*64, mlp_g+2*64, mlp_beta+2*64,
            B.huS, NPREDN, B.stat + 3*128);

    // 11. fused gating + final MLPs
    k_softmul2<<<ceil_div(NPREDN*16,256),256>>>(B.huP, B.huS, B.mA, B.mA2, NPREDN);
    run_mlp(B, B.mA, B.huP, mlp_W+3*8192, mlp_b+3*64, mlp_g+3*64, mlp_beta+3*64,
            out, NPREDN, B.stat + 4*128);
    run_mlp(B, B.mA2, B.huS, mlp_W+4*8192, mlp_b+4*64, mlp_g+4*64, mlp_beta+4*64,
            out + (size_t)NPREDN*EMBD, NPREDN, B.stat + 5*128);
}

// round 17
// speedup vs baseline: 1.4858x; 1.0512x over previous
#include <cuda_runtime.h>
#include <cuda_fp16.h>
#include <math.h>

#define NPREDN 100000
#define NTOTN  120000
#define NUIN   200000
#define NNODESN 220000
#define EMBD 64
#define MAXE 1500000
#define RPSZ 200001
#define XSTRIDE 66   // transposed X tile row stride (floats): even -> 8B aligned pairs

typedef unsigned long long ull;

// ---------------- device scratch (static, no allocations) ----------------
__device__ float  g_ebn[NNODESN*EMBD];
__device__ float  g_uie[NUIN*EMBD];
__device__ __half g_fsh[NUIN*EMBD];     // fp16 GAT intermediates
__device__ __half g_fdh[NUIN*EMBD];
__device__ float  g_gout[NUIN*EMBD];
__device__ float  g_u2i[NUIN*EMBD];
__device__ float  g_rc[NUIN*EMBD];
__device__ float  g_T1[NTOTN*EMBD];
__device__ float  g_T2[NTOTN*EMBD];
__device__ float  g_ch[NTOTN*EMBD];
__device__ float  g_ch2[NTOTN*EMBD];
__device__ float  g_i2u[NPREDN*EMBD];
__device__ float  g_soc[NPREDN*EMBD];
__device__ float  g_sie[NPREDN*EMBD];
__device__ float  g_uitem[NPREDN*EMBD];
__device__ float  g_huP[NPREDN*EMBD];
__device__ float  g_huS[NPREDN*EMBD];
__device__ float  g_mA[NPREDN*EMBD];
__device__ float  g_mA2[NPREDN*EMBD];
__device__ float  g_z[NPREDN*EMBD];
__device__ float  g_stat[6*128];
// CSR sort scratch
__device__ int    g_srcs[7000000];
__device__ int    g_rowptr[5*RPSZ];
__device__ int    g_cnt[RPSZ];
__device__ int    g_pos[RPSZ];
__device__ int    g_part[256];
__device__ float  g_deginv[NTOTN];
__device__ float  g_normv[MAXE];

static inline int ceil_div(int a, int b) { return (a + b - 1) / b; }

__device__ __forceinline__ float lrelu(float v, float s) { return v > 0.f ? v : s*v; }

__device__ __forceinline__ ull dup_f(float x) {
    ull r; asm("mov.b64 %0, {%1,%1};" : "=l"(r) : "f"(x)); return r;
}
__device__ __forceinline__ float2 unpk(ull v) {
    float2 r; asm("mov.b64 {%0,%1}, %2;" : "=f"(r.x), "=f"(r.y) : "l"(v)); return r;
}
__device__ __forceinline__ void ffma2(ull& acc, ull a, ull b) {
    asm("fma.rn.f32x2 %0, %1, %2, %0;" : "+l"(acc) : "l"(a), "l"(b));
}

// load 4 halves (one uint2) -> float4
__device__ __forceinline__ float4 ldh4(const __half* p, size_t idx)
{
    uint2 q = ((const uint2*)p)[idx];
    __half2 h01 = *(__half2*)&q.x;
    __half2 h23 = *(__half2*)&q.y;
    float2 a = __half22float2(h01);
    float2 b = __half22float2(h23);
    return make_float4(a.x, a.y, b.x, b.y);
}

// ====== GEMM family: 64-row blocks, 128 threads, 8 rows x 4 cols per thread =======
__device__ __forceinline__ void load_x64_t(const float* __restrict__ X,
                                           const int* __restrict__ ids,
                                           float* Xt, int row0, int n, int tid)
{
    #pragma unroll
    for (int i = 0; i < 8; i++) {
        int idx = tid + i*128;
        int r = idx >> 4, c4 = idx & 15;
        int gr = row0 + r;
        float4 v = make_float4(0.f,0.f,0.f,0.f);
        if (gr < n) {
            int sr = ids ? ids[gr] : gr;
            v = ((const float4*)X)[(size_t)sr*16 + c4];
        }
        int k0 = c4*4;
        Xt[(k0+0)*XSTRIDE + r] = v.x;
        Xt[(k0+1)*XSTRIDE + r] = v.y;
        Xt[(k0+2)*XSTRIDE + r] = v.z;
        Xt[(k0+3)*XSTRIDE + r] = v.w;
    }
}
__device__ __forceinline__ void load_w64(const float* __restrict__ W, float* Ws, int tid)
{
    #pragma unroll
    for (int i = 0; i < 8; i++)
        ((float4*)Ws)[tid + i*128] = ((const float4*)W)[tid + i*128];
}

__device__ __forceinline__ void mm_f2t(const float* Xt, const float* Ws,
                                       ull acc[4][4], int tx, int ty)
{
    #pragma unroll 8
    for (int k = 0; k < 64; k++) {
        float4 b = *(const float4*)&Ws[k*64 + tx*4];
        ull b0 = dup_f(b.x), b1 = dup_f(b.y), b2 = dup_f(b.z), b3 = dup_f(b.w);
        const ull* ap = (const ull*)&Xt[k*XSTRIDE + ty*8];
        #pragma unroll
        for (int i = 0; i < 4; i++) {
            ull a = ap[i];
            ffma2(acc[i][0], a, b0);
            ffma2(acc[i][1], a, b1);
            ffma2(acc[i][2], a, b2);
            ffma2(acc[i][3], a, b3);
        }
    }
}

__device__ __forceinline__ void unpack_acc(ull acc[4][4], float f[8][4])
{
    #pragma unroll
    for (int i = 0; i < 4; i++) {
        #pragma unroll
        for (int j = 0; j < 4; j++) {
            float2 p = unpk(acc[i][j]);
            f[2*i][j]   = p.x;
            f[2*i+1][j] = p.y;
        }
    }
}

__device__ __forceinline__ void store8x4(float* __restrict__ Y, float f[8][4],
                                         const float* __restrict__ bias,
                                         int row0, int n, int tx, int ty, int act)
{
    float4 bb = bias ? ((const float4*)bias)[tx] : make_float4(0.f,0.f,0.f,0.f);
    #pragma unroll
    for (int i = 0; i < 8; i++) {
        int gr = row0 + ty*8 + i;
        if (gr < n) {
            float4 v = make_float4(f[i][0]+bb.x, f[i][1]+bb.y, f[i][2]+bb.z, f[i][3]+bb.w);
            if (act) { v.x=lrelu(v.x,0.01f); v.y=lrelu(v.y,0.01f);
                       v.z=lrelu(v.z,0.01f); v.w=lrelu(v.w,0.01f); }
            ((float4*)Y)[(size_t)gr*16 + tx] = v;
        }
    }
}

// half-precision store (GAT intermediates): row = 64 halves = 16 uint2
__device__ __forceinline__ void store8x4h(__half* __restrict__ Y, float f[8][4],
                                          const float* __restrict__ bias,
                                          int row0, int n, int tx, int ty)
{
    float4 bb = bias ? ((const float4*)bias)[tx] : make_float4(0.f,0.f,0.f,0.f);
    #pragma unroll
    for (int i = 0; i < 8; i++) {
        int gr = row0 + ty*8 + i;
        if (gr < n) {
            __half2 h01 = __floats2half2_rn(f[i][0]+bb.x, f[i][1]+bb.y);
            __half2 h23 = __floats2half2_rn(f[i][2]+bb.z, f[i][3]+bb.w);
            uint2 u = make_uint2(*(unsigned*)&h01, *(unsigned*)&h23);
            ((uint2*)Y)[(size_t)gr*16 + tx] = u;
        }
    }
}

__device__ __forceinline__ void stats_epilogue(float f[8][4], float* sh,
                                               const float* __restrict__ bias,
                                               float* __restrict__ stat,
                                               int row0, int n, int tx, int ty, int tid)
{
    float4 bb = bias ? ((const float4*)bias)[tx] : make_float4(0.f,0.f,0.f,0.f);
    float s[4] = {0,0,0,0}, q[4] = {0,0,0,0};
    #pragma unroll
    for (int i = 0; i < 8; i++) {
        int gr = row0 + ty*8 + i;
        if (gr < n) {
            float v0 = f[i][0]+bb.x, v1 = f[i][1]+bb.y;
            float v2 = f[i][2]+bb.z, v3 = f[i][3]+bb.w;
            s[0]+=v0; s[1]+=v1; s[2]+=v2; s[3]+=v3;
            q[0]+=v0*v0; q[1]+=v1*v1; q[2]+=v2*v2; q[3]+=v3*v3;
        }
    }
    __syncthreads();
    #pragma unroll
    for (int k = 0; k < 4; k++) {
        sh[ty*128 + tx*8 + k]     = s[k];
        sh[ty*128 + tx*8 + 4 + k] = q[k];
    }
    __syncthreads();
    if (tid < 128) {
        float t = 0.f;
        #pragma unroll
        for (int w = 0; w < 8; w++) t += sh[w*128 + tid];
        int txx = tid >> 3, qq = tid & 7;
        int col = txx*4 + (qq & 3);
        atomicAdd(&stat[(qq < 4 ? col : 64 + col)], t);
    }
}

// fs = X@W1+b1 ; fd = X@W2+b2, both stored fp16
__global__ void __launch_bounds__(128) k_gemm_dual(
    const float* __restrict__ X, const int* __restrict__ ids,
    const float* __restrict__ W1, const float* __restrict__ b1, __half* __restrict__ Y1,
    const float* __restrict__ W2, const float* __restrict__ b2, __half* __restrict__ Y2,
    int n)
{
    __shared__ float Xt[64*XSTRIDE];
    __shared__ float Ws[4096];
    int tid = threadIdx.x, tx = tid & 15, ty = tid >> 4;
    int row0 = blockIdx.x * 64;
    load_x64_t(X, ids, Xt, row0, n, tid);
    load_w64(W1, Ws, tid);
    __syncthreads();
    {
        ull acc[4][4] = {};
        mm_f2t(Xt, Ws, acc, tx, ty);
        float f[8][4]; unpack_acc(acc, f);
        store8x4h(Y1, f, b1, row0, n, tx, ty);
    }
    __syncthreads();
    load_w64(W2, Ws, tid);
    __syncthreads();
    {
        ull acc[4][4] = {};
        mm_f2t(Xt, Ws, acc, tx, ty);
        float f[8][4]; unpack_acc(acc, f);
        store8x4h(Y2, f, b2, row0, n, tx, ty);
    }
}

__global__ void __launch_bounds__(128) k_gemm_cat(
    const float* __restrict__ A, const float* __restrict__ Bx,
    const float* __restrict__ W, const float* __restrict__ bias,
    float* __restrict__ Y, int n, float* __restrict__ stat)
{
    __shared__ float Xt[64*XSTRIDE];
    __shared__ float Ws[4096];
    int tid = threadIdx.x, tx = tid & 15, ty = tid >> 4;
    int row0 = blockIdx.x * 64;
    ull acc[4][4] = {};
    load_x64_t(A, nullptr, Xt, row0, n, tid);
    load_w64(W, Ws, tid);
    __syncthreads();
    mm_f2t(Xt, Ws, acc, tx, ty);
    __syncthreads();
    load_x64_t(Bx, nullptr, Xt, row0, n, tid);
    load_w64(W + 4096, Ws, tid);
    __syncthreads();
    mm_f2t(Xt, Ws, acc, tx, ty);
    float f[8][4]; unpack_acc(acc, f);
    store8x4(Y, f, bias, row0, n, tx, ty, 0);
    if (stat) stats_epilogue(f, Ws, bias, stat, row0, n, tx, ty, tid);
}

// cheb: Y = lrelu(X0@W0 + X1@W1 + X2c@W2 + bias); X2c pre-combined (2*lhat(T1)-T0)
__global__ void __launch_bounds__(128) k_gemm_cat3(
    const float* __restrict__ X0, const float* __restrict__ X1, const float* __restrict__ X2c,
    const float* __restrict__ W, const float* __restrict__ bias,
    float* __restrict__ Y, int n)
{
    __shared__ float Xt[64*XSTRIDE];
    __shared__ float Ws[4096];
    int tid = threadIdx.x, tx = tid & 15, ty = tid >> 4;
    int row0 = blockIdx.x * 64;
    ull acc[4][4] = {};
    load_x64_t(X0, nullptr, Xt, row0, n, tid);
    load_w64(W, Ws, tid);
    __syncthreads();
    mm_f2t(Xt, Ws, acc, tx, ty);
    __syncthreads();
    load_x64_t(X1, nullptr, Xt, row0, n, tid);
    load_w64(W + 4096, Ws, tid);
    __syncthreads();
    mm_f2t(Xt, Ws, acc, tx, ty);
    __syncthreads();
    load_x64_t(X2c, nullptr, Xt, row0, n, tid);
    load_w64(W + 8192, Ws, tid);
    __syncthreads();
    mm_f2t(Xt, Ws, acc, tx, ty);
    float f[8][4]; unpack_acc(acc, f);
    store8x4(Y, f, bias, row0, n, tx, ty, 1);
}

// ---------------- BN ----------------
__global__ void k_colstats(const float* __restrict__ X, int n, float* __restrict__ stat)
{
    int c  = threadIdx.x & 63;
    int tg = threadIdx.x >> 6;
    float s = 0.f, sq = 0.f;
    for (int r = blockIdx.x*4 + tg; r < n; r += gridDim.x*4) {
        float v = X[(size_t)r*64 + c];
        s += v; sq += v*v;
    }
    __shared__ float sh[4][128];
    sh[tg][c] = s; sh[tg][64+c] = sq;
    __syncthreads();
    if (tg == 0) {
        float ts = sh[0][c]+sh[1][c]+sh[2][c]+sh[3][c];
        float tq = sh[0][64+c]+sh[1][64+c]+sh[2][64+c]+sh[3][64+c];
        atomicAdd(&stat[c], ts);
        atomicAdd(&stat[64+c], tq);
    }
}

__device__ __forceinline__ float4 bn4(float4 x, float4 s1, float4 s2,
                                      float4 gg, float4 bb, float invn)
{
    float4 o;
    float mu = s1.x*invn, var = s2.x*invn - mu*mu;
    o.x = (x.x-mu)*rsqrtf(var+1e-5f)*gg.x + bb.x;
    mu = s1.y*invn; var = s2.y*invn - mu*mu;
    o.y = (x.y-mu)*rsqrtf(var+1e-5f)*gg.y + bb.y;
    mu = s1.z*invn; var = s2.z*invn - mu*mu;
    o.z = (x.z-mu)*rsqrtf(var+1e-5f)*gg.z + bb.z;
    mu = s1.w*invn; var = s2.w*invn - mu*mu;
    o.w = (x.w-mu)*rsqrtf(var+1e-5f)*gg.w + bb.w;
    return o;
}

__global__ void k_bnapply(const float* __restrict__ X, const float* __restrict__ stat,
                          const float* __restrict__ g, const float* __restrict__ b,
                          float* __restrict__ Y, int nq, float invn, int act)
{
    int i = blockIdx.x*blockDim.x + threadIdx.x;
    if (i >= nq) return;
    int c4 = i & 15;
    float4 o = bn4(((const float4*)X)[i], ((const float4*)stat)[c4],
                   ((const float4*)stat)[16+c4], ((const float4*)g)[c4],
                   ((const float4*)b)[c4], invn);
    if (act) { o.x=lrelu(o.x,0.01f); o.y=lrelu(o.y,0.01f);
               o.z=lrelu(o.z,0.01f); o.w=lrelu(o.w,0.01f); }
    ((float4*)Y)[i] = o;
}

__global__ void k_bnapply_uie(const float* __restrict__ X, const float* __restrict__ stat,
                              const float* __restrict__ g, const float* __restrict__ b,
                              float* __restrict__ ebn, float* __restrict__ uie, float invn)
{
    int i = blockIdx.x*blockDim.x + threadIdx.x;
    if (i >= NNODESN*16) return;
    int c4 = i & 15;
    float4 o = bn4(((const float4*)X)[i], ((const float4*)stat)[c4],
                   ((const float4*)stat)[16+c4], ((const float4*)g)[c4],
                   ((const float4*)b)[c4], invn);
    ((float4*)ebn)[i] = o;
    int row = i >> 4;
    if (row < NPREDN) ((float4*)uie)[i] = o;
    else if (row >= NNODESN - 100000)
        ((float4*)uie)[(size_t)(row - (NNODESN - NUIN))*16 + c4] = o;
}

// ================= counting sort by dst (CSR build) =================
__global__ void k_hist(const int* __restrict__ dst, int ne, int* __restrict__ cnt)
{
    int i = blockIdx.x*blockDim.x + threadIdx.x;
    if (i < ne) atomicAdd(&cnt[dst[i]], 1);
}
__global__ void k_scan_part(const int* __restrict__ cnt, int n, int* __restrict__ part)
{
    __shared__ int sh[256];
    int t = threadIdx.x, base = blockIdx.x*1024 + t*4;
    int s = 0;
    #pragma unroll
    for (int j = 0; j < 4; j++) { int i = base+j; if (i < n) s += cnt[i]; }
    sh[t] = s; __syncthreads();
    #pragma unroll
    for (int off = 128; off; off >>= 1) {
        if (t < off) sh[t] += sh[t+off];
        __syncthreads();
    }
    if (!t) part[blockIdx.x] = sh[0];
}
__global__ void k_scan_top(int* __restrict__ part, int nb, int* __restrict__ totptr)
{
    __shared__ int sh[256];
    int t = threadIdx.x;
    int v = t < nb ? part[t] : 0;
    sh[t] = v; __syncthreads();
    for (int off = 1; off < 256; off <<= 1) {
        int u = t >= off ? sh[t-off] : 0;
        __syncthreads();
        sh[t] += u;
        __syncthreads();
    }
    int excl = t ? sh[t-1] : 0;
    if (t < nb) part[t] = excl;
    if (t == 255) *totptr = sh[255];
}
__global__ void k_scan_final(const int* __restrict__ cnt, const int* __restrict__ part, int n,
                             int* __restrict__ rowptr, int* __restrict__ pos)
{
    __shared__ int sh[256];
    int t = threadIdx.x, base = blockIdx.x*1024 + t*4;
    int c[4]; int s = 0;
    #pragma unroll
    for (int j = 0; j < 4; j++) { int i = base+j; c[j] = (i < n) ? cnt[i] : 0; s += c[j]; }
    sh[t] = s; __syncthreads();
    for (int off = 1; off < 256; off <<= 1) {
        int u = t >= off ? sh[t-off] : 0;
        __syncthreads();
        sh[t] += u;
        __syncthreads();
    }
    int run = (t ? sh[t-1] : 0) + part[blockIdx.x];
    #pragma unroll
    for (int j = 0; j < 4; j++) {
        int i = base+j;
        if (i < n) { rowptr[i] = run; pos[i] = run; }
        run += c[j];
    }
}
__global__ void k_scatter(const int* __restrict__ src, const int* __restrict__ dst, int ne,
                          int* __restrict__ pos, int* __restrict__ srcs)
{
    int i = blockIdx.x*blockDim.x + threadIdx.x;
    if (i >= ne) return;
    int p = atomicAdd(&pos[dst[i]], 1);
    srcs[p] = src[i];
}
__global__ void k_deginv(const int* __restrict__ rowptr, float* __restrict__ dinv, int n)
{
    int i = blockIdx.x*blockDim.x + threadIdx.x;
    if (i < n) dinv[i] = rsqrtf(fmaxf((float)(rowptr[i+1]-rowptr[i]), 1.f));
}
__global__ void k_scatter_norm(const int* __restrict__ src, const int* __restrict__ dst, int ne,
                               int* __restrict__ pos, const float* __restrict__ dinv,
                               int* __restrict__ srcs, float* __restrict__ normv)
{
    int i = blockIdx.x*blockDim.x + threadIdx.x;
    if (i >= ne) return;
    int s = src[i], d = dst[i];
    int p = atomicAdd(&pos[d], 1);
    srcs[p] = s;
    normv[p] = dinv[s]*dinv[d];
}

// ========== node-parallel GAT aggregation (16 lanes/node, fp16 fs/fd gathers) ==========
__global__ void k_gat_node(const int* __restrict__ rowptr, const int* __restrict__ srcs,
                           const __half* __restrict__ fs, const __half* __restrict__ fd,
                           const float* __restrict__ attn, float* __restrict__ out, int n)
{
    int w = (blockIdx.x*blockDim.x + threadIdx.x) >> 4;
    int l = threadIdx.x & 15;
    unsigned mask = 0xFFFFu << (threadIdx.x & 16);
    if (w >= n) return;
    int beg = rowptr[w], end = rowptr[w+1];
    float4 fdv = ldh4(fd, (size_t)w*16 + l);
    float4 at  = ((const float4*)attn)[l];
    float4 acc = make_float4(0.f,0.f,0.f,0.f);
    float den = 0.f;
    int e = beg;
    for (; e+4 <= end; e += 4) {
        int s0 = srcs[e], s1 = srcs[e+1], s2 = srcs[e+2], s3 = srcs[e+3];
        float4 f0 = ldh4(fs, (size_t)s0*16 + l);
        float4 f1 = ldh4(fs, (size_t)s1*16 + l);
        float4 f2 = ldh4(fs, (size_t)s2*16 + l);
        float4 f3 = ldh4(fs, (size_t)s3*16 + l);
        float t0 = lrelu(f0.x+fdv.x,0.2f)*at.x + lrelu(f0.y+fdv.y,0.2f)*at.y
                 + lrelu(f0.z+fdv.z,0.2f)*at.z + lrelu(f0.w+fdv.w,0.2f)*at.w;
        float t1 = lrelu(f1.x+fdv.x,0.2f)*at.x + lrelu(f1.y+fdv.y,0.2f)*at.y
                 + lrelu(f1.z+fdv.z,0.2f)*at.z + lrelu(f1.w+fdv.w,0.2f)*at.w;
        float t2 = lrelu(f2.x+fdv.x,0.2f)*at.x + lrelu(f2.y+fdv.y,0.2f)*at.y
                 + lrelu(f2.z+fdv.z,0.2f)*at.z + lrelu(f2.w+fdv.w,0.2f)*at.w;
        float t3 = lrelu(f3.x+fdv.x,0.2f)*at.x + lrelu(f3.y+fdv.y,0.2f)*at.y
                 + lrelu(f3.z+fdv.z,0.2f)*at.z + lrelu(f3.w+fdv.w,0.2f)*at.w;
        #pragma unroll
        for (int o = 8; o; o >>= 1) {
            t0 += __shfl_xor_sync(mask, t0, o, 16);
            t1 += __shfl_xor_sync(mask, t1, o, 16);
            t2 += __shfl_xor_sync(mask, t2, o, 16);
            t3 += __shfl_xor_sync(mask, t3, o, 16);
        }
        float e0 = __expf(t0), e1 = __expf(t1), e2 = __expf(t2), e3 = __expf(t3);
        den += (e0 + e1) + (e2 + e3);
        acc.x += e0*f0.x + e1*f1.x + e2*f2.x + e3*f3.x;
        acc.y += e0*f0.y + e1*f1.y + e2*f2.y + e3*f3.y;
        acc.z += e0*f0.z + e1*f1.z + e2*f2.z + e3*f3.z;
        acc.w += e0*f0.w + e1*f1.w + e2*f2.w + e3*f3.w;
    }
    for (; e < end; e++) {
        int s0 = srcs[e];
        float4 f0 = ldh4(fs, (size_t)s0*16 + l);
        float t0 = lrelu(f0.x+fdv.x,0.2f)*at.x + lrelu(f0.y+fdv.y,0.2f)*at.y
                 + lrelu(f0.z+fdv.z,0.2f)*at.z + lrelu(f0.w+fdv.w,0.2f)*at.w;
        #pragma unroll
        for (int o = 8; o; o >>= 1) t0 += __shfl_xor_sync(mask, t0, o, 16);
        float e0 = __expf(t0);
        den += e0;
        acc.x += e0*f0.x; acc.y += e0*f0.y; acc.z += e0*f0.z; acc.w += e0*f0.w;
    }
    float inv = den > 0.f ? 1.f/den : 0.f;
    ((float4*)out)[(size_t)w*16 + l] =
        make_float4(lrelu(acc.x*inv,0.01f), lrelu(acc.y*inv,0.01f),
                    lrelu(acc.z*inv,0.01f), lrelu(acc.w*inv,0.01f));
}

// node-parallel lhat (16 lanes/node, 4-edge MLP) — stays fp32
__global__ void k_lhat_node(const int* __restrict__ rowptr, const int* __restrict__ srcs,
                            const float* __restrict__ normv, const float* __restrict__ v,
                            const float* __restrict__ lamp, const float* __restrict__ t0arr,
                            float* __restrict__ out, int n)
{
    int w = (blockIdx.x*blockDim.x + threadIdx.x) >> 4;
    int l = threadIdx.x & 15;
    if (w >= n) return;
    int beg = rowptr[w], end = rowptr[w+1];
    float4 acc = make_float4(0.f,0.f,0.f,0.f);
    int e = beg;
    for (; e+4 <= end; e += 4) {
        int s0 = srcs[e], s1 = srcs[e+1], s2 = srcs[e+2], s3 = srcs[e+3];
        float n0 = normv[e], n1 = normv[e+1], n2 = normv[e+2], n3 = normv[e+3];
        float4 f0 = ((const float4*)v)[(size_t)s0*16 + l];
        float4 f1 = ((const float4*)v)[(size_t)s1*16 + l];
        float4 f2 = ((const float4*)v)[(size_t)s2*16 + l];
        float4 f3 = ((const float4*)v)[(size_t)s3*16 + l];
        acc.x += (n0*f0.x + n1*f1.x) + (n2*f2.x + n3*f3.x);
        acc.y += (n0*f0.y + n1*f1.y) + (n2*f2.y + n3*f3.y);
        acc.z += (n0*f0.z + n1*f1.z) + (n2*f2.z + n3*f3.z);
        acc.w += (n0*f0.w + n1*f1.w) + (n2*f2.w + n3*f3.w);
    }
    for (; e < end; e++) {
        int s0 = srcs[e];
        float n0 = normv[e];
        float4 f0 = ((const float4*)v)[(size_t)s0*16 + l];
        acc.x += n0*f0.x; acc.y += n0*f0.y; acc.z += n0*f0.z; acc.w += n0*f0.w;
    }
    float c = 2.f / __ldg(lamp);
    float4 vv = ((const float4*)v)[(size_t)w*16 + l];
    float4 o = make_float4(c*(vv.x-acc.x)-vv.x, c*(vv.y-acc.y)-vv.y,
                           c*(vv.z-acc.z)-vv.z, c*(vv.w-acc.w)-vv.w);
    if (t0arr) {
        float4 t0 = ((const float4*)t0arr)[(size_t)w*16 + l];
        o = make_float4(2.f*o.x-t0.x, 2.f*o.y-t0.y, 2.f*o.z-t0.z, 2.f*o.w-t0.w);
    }
    ((float4*)out)[(size_t)w*16 + l] = o;
}

// ---------------- misc ----------------
// fused soc build: soc[ids[r]] = (sum(i2u[r]) != 0) ? i2u[r] : uie[ids[r]]
__global__ void k_socmerge(const float* __restrict__ i2u, const float* __restrict__ uie,
                           const int* __restrict__ ids, float* __restrict__ soc, int n)
{
    int t = blockIdx.x*blockDim.x + threadIdx.x;
    int r = t >> 4, l = t & 15;
    if (r >= n) return;
    float4 v = ((const float4*)i2u)[(size_t)r*16 + l];
    float s = v.x + v.y + v.z + v.w;
    unsigned mask = 0xFFFFu << (threadIdx.x & 16);
    #pragma unroll
    for (int o = 8; o; o >>= 1) s += __shfl_xor_sync(mask, s, o, 16);
    int tr = ids[r];
    float4 u = ((const float4*)uie)[(size_t)tr*16 + l];
    ((float4*)soc)[(size_t)tr*16 + l] = (s != 0.f) ? v : u;
}
__global__ void k_softmul2(const float* __restrict__ hP, const float* __restrict__ hS,
                           float* __restrict__ mAP, float* __restrict__ mAS, int n)
{
    int t = blockIdx.x*blockDim.x + threadIdx.x;
    int r = t >> 4, l = t & 15;
    unsigned mask = 0xFFFFu << (threadIdx.x & 16);
    if (r >= n) return;
    size_t base = (size_t)r*16 + l;
    float4 p = ((const float4*)hP)[base];
    float4 s = ((const float4*)hS)[base];
    float mp = fmaxf(fmaxf(p.x,p.y), fmaxf(p.z,p.w));
    float ms = fmaxf(fmaxf(s.x,s.y), fmaxf(s.z,s.w));
    #pragma unroll
    for (int o = 8; o; o >>= 1) {
        mp = fmaxf(mp, __shfl_xor_sync(mask, mp, o, 16));
        ms = fmaxf(ms, __shfl_xor_sync(mask, ms, o, 16));
    }
    float4 eP = make_float4(__expf(p.x-mp), __expf(p.y-mp), __expf(p.z-mp), __expf(p.w-mp));
    float4 eS = make_float4(__expf(s.x-ms), __expf(s.y-ms), __expf(s.z-ms), __expf(s.w-ms));
    float sp = eP.x+eP.y+eP.z+eP.w;
    float ss = eS.x+eS.y+eS.z+eS.w;
    #pragma unroll
    for (int o = 8; o; o >>= 1) {
        sp += __shfl_xor_sync(mask, sp, o, 16);
        ss += __shfl_xor_sync(mask, ss, o, 16);
    }
    float ip = 1.f/sp, is = 1.f/ss;
    float4 hm = make_float4(p.x*s.x, p.y*s.y, p.z*s.z, p.w*s.w);
    ((float4*)mAP)[base] = make_float4(hm.x*eP.x*ip, hm.y*eP.y*ip, hm.z*eP.z*ip, hm.w*eP.w*ip);
    ((float4*)mAS)[base] = make_float4(hm.x*eS.x*is, hm.y*eS.y*is, hm.z*eS.z*is, hm.w*eS.w*is);
}

// ---------------- host-side composition ----------------
struct Bufs {
    float *ebn,*uie,*gout,*u2i,*rc,*T1,*T2,*ch,*ch2,*i2u,*soc,*sie,
          *uitem,*huP,*huS,*mA,*mA2,*z,*stat,*deginv,*normv;
    __half *fsh,*fdh;
    int *srcs,*rowptr,*cnt,*pos,*part;
};
static void get_bufs(Bufs& B) {
    cudaGetSymbolAddress((void**)&B.ebn,  g_ebn);
    cudaGetSymbolAddress((void**)&B.uie,  g_uie);
    cudaGetSymbolAddress((void**)&B.fsh,  g_fsh);
    cudaGetSymbolAddress((void**)&B.fdh,  g_fdh);
    cudaGetSymbolAddress((void**)&B.gout, g_gout);
    cudaGetSymbolAddress((void**)&B.u2i,  g_u2i);
    cudaGetSymbolAddress((void**)&B.rc,   g_rc);
    cudaGetSymbolAddress((void**)&B.T1,   g_T1);
    cudaGetSymbolAddress((void**)&B.T2,   g_T2);
    cudaGetSymbolAddress((void**)&B.ch,   g_ch);
    cudaGetSymbolAddress((void**)&B.ch2,  g_ch2);
    cudaGetSymbolAddress((void**)&B.i2u,  g_i2u);
    cudaGetSymbolAddress((void**)&B.soc,  g_soc);
    cudaGetSymbolAddress((void**)&B.sie,  g_sie);
    cudaGetSymbolAddress((void**)&B.uitem,g_uitem);
    cudaGetSymbolAddress((void**)&B.huP,  g_huP);
    cudaGetSymbolAddress((void**)&B.huS,  g_huS);
    cudaGetSymbolAddress((void**)&B.mA,   g_mA);
    cudaGetSymbolAddress((void**)&B.mA2,  g_mA2);
    cudaGetSymbolAddress((void**)&B.z,    g_z);
    cudaGetSymbolAddress((void**)&B.stat, g_stat);
    cudaGetSymbolAddress((void**)&B.deginv, g_deginv);
    cudaGetSymbolAddress((void**)&B.normv,  g_normv);
    cudaGetSymbolAddress((void**)&B.srcs,   g_srcs);
    cudaGetSymbolAddress((void**)&B.rowptr, g_rowptr);
    cudaGetSymbolAddress((void**)&B.cnt,    g_cnt);
    cudaGetSymbolAddress((void**)&B.pos,    g_pos);
    cudaGetSymbolAddress((void**)&B.part,   g_part);
}

static void sort_graph(Bufs& B, const int* src, const int* dst, int ne, int n,
                       int* rowptr, int* srcs, bool with_norm)
{
    cudaMemsetAsync(B.cnt, 0, (size_t)n*4);
    k_hist<<<ceil_div(ne,256),256>>>(dst, ne, B.cnt);
    int nb = ceil_div(n, 1024);
    k_scan_part<<<nb,256>>>(B.cnt, n, B.part);
    k_scan_top<<<1,256>>>(B.part, nb, rowptr + n);
    k_scan_final<<<nb,256>>>(B.cnt, B.part, n, rowptr, B.pos);
    if (with_norm) {
        k_deginv<<<ceil_div(n,256),256>>>(rowptr, B.deginv, n);
        k_scatter_norm<<<ceil_div(ne,256),256>>>(src, dst, ne, B.pos, B.deginv,
                                                 srcs, B.normv);
    } else {
        k_scatter<<<ceil_div(ne,256),256>>>(src, dst, ne, B.pos, srcs);
    }
}

static void run_gat(Bufs& B, const int* rowptr, const int* srcs,
                    const float* x, const int* ids, int n,
                    const float* Wl, const float* bl,
                    const float* Wr, const float* br,
                    const float* attn, float* out)
{
    k_gemm_dual<<<ceil_div(n,64),128>>>(x, ids, Wl, bl, B.fsh, Wr, br, B.fdh, n);
    k_gat_node<<<ceil_div(n*16,256),256>>>(rowptr, srcs, B.fsh, B.fdh, attn, out, n);
}

static void run_mlp(Bufs& B, const float* A, const float* Bx, const float* W,
                    const float* b, const float* g, const float* beta,
                    float* out, int n, float* stat)
{
    k_gemm_cat<<<ceil_div(n,64),128>>>(A, Bx, W, b, B.z, n, stat);
    k_bnapply<<<ceil_div(n*16,256),256>>>(B.z, stat, g, beta, out, n*16, 1.0f/n, 1);
}

extern "C" void kernel_launch(void* const* d_in, const int* in_sizes, int n_in,
                              void* d_out, int out_size)
{
    const float* emb      = (const float*)d_in[0];
    const float* bn0_g    = (const float*)d_in[1];
    const float* bn0_b    = (const float*)d_in[2];
    const float* gat_Wl   = (const float*)d_in[3];
    const float* gat_bl   = (const float*)d_in[4];
    const float* gat_Wr   = (const float*)d_in[5];
    const float* gat_br   = (const float*)d_in[6];
    const float* gat_attn = (const float*)d_in[7];
    const float* cheb_W   = (const float*)d_in[8];
    const float* cheb_b   = (const float*)d_in[9];
    const float* mlp_W    = (const float*)d_in[10];
    const float* mlp_b    = (const float*)d_in[11];
    const float* mlp_g    = (const float*)d_in[12];
    const float* mlp_beta = (const float*)d_in[13];
    const float* lam      = (const float*)d_in[14];
    const int* u2i_src = (const int*)d_in[15]; const int* u2i_dst = (const int*)d_in[16];
    const int* rc_src  = (const int*)d_in[17]; const int* rc_dst  = (const int*)d_in[18];
    const int* i2u_src = (const int*)d_in[19]; const int* i2u_dst = (const int*)d_in[20];
    const int* i2u_ids = (const int*)d_in[21];
    const int* sn_src  = (const int*)d_in[22]; const int* sn_dst  = (const int*)d_in[23];
    const int* snn_src = (const int*)d_in[24]; const int* snn_dst = (const int*)d_in[25];

    int ne_u2i = in_sizes[15], ne_rc = in_sizes[17], ne_i2u = in_sizes[19];
    int ne_sn  = in_sizes[22], ne_snn = in_sizes[24];

    float* out = (float*)d_out;
    Bufs B; get_bufs(B);

    int* rp_u2i = B.rowptr + 0*RPSZ; int* sc_u2i = B.srcs + 0;
    int* rp_rc  = B.rowptr + 1*RPSZ; int* sc_rc  = B.srcs + 1500000;
    int* rp_i2u = B.rowptr + 2*RPSZ; int* sc_i2u = B.srcs + 3000000;
    int* rp_sn  = B.rowptr + 3*RPSZ; int* sc_sn  = B.srcs + 4000000;
    int* rp_snn = B.rowptr + 4*RPSZ; int* sc_snn = B.srcs + 5000000;

    cudaMemsetAsync(B.stat, 0, 6*128*4);

    sort_graph(B, u2i_src, u2i_dst, ne_u2i, NUIN,   rp_u2i, sc_u2i, false);
    sort_graph(B, rc_src,  rc_dst,  ne_rc,  NUIN,   rp_rc,  sc_rc,  false);
    sort_graph(B, i2u_src, i2u_dst, ne_i2u, NPREDN, rp_i2u, sc_i2u, false);
    sort_graph(B, sn_src,  sn_dst,  ne_sn,  NPREDN, rp_sn,  sc_sn,  false);
    sort_graph(B, snn_src, snn_dst, ne_snn, NTOTN,  rp_snn, sc_snn, true);

    // 1. e = BN(emb); fused uie
    k_colstats<<<512,256>>>(emb, NNODESN, B.stat);
    k_bnapply_uie<<<ceil_div(NNODESN*16,256),256>>>(emb, B.stat, bn0_g, bn0_b,
                                                    B.ebn, B.uie, 1.0f/NNODESN);

    // 2. GAT0 (u2i), GAT1 (rc)
    run_gat(B, rp_u2i, sc_u2i, B.uie, nullptr, NUIN,
            gat_Wl+0*4096, gat_bl+0*64, gat_Wr+0*4096, gat_br+0*64, gat_attn+0*64, B.u2i);
    run_gat(B, rp_rc, sc_rc, B.u2i, nullptr, NUIN,
            gat_Wl+1*4096, gat_bl+1*64, gat_Wr+1*4096, gat_br+1*64, gat_attn+1*64, B.rc);

    // 3. GAT2 on su = uie[i2u_ids]
    run_gat(B, rp_i2u, sc_i2u, B.uie, i2u_ids, NPREDN,
            gat_Wl+2*4096, gat_bl+2*64, gat_Wr+2*4096, gat_br+2*64, gat_attn+2*64, B.i2u);

    // 4. soc (fused copy + mask-merge)
    k_socmerge<<<ceil_div(NPREDN*16,256),256>>>(B.i2u, B.uie, i2u_ids, B.soc, NPREDN);

    // 5. GAT3 (sn)
    run_gat(B, rp_sn, sc_sn, B.soc, nullptr, NPREDN,
            gat_Wl+3*4096, gat_bl+3*64, gat_Wr+3*4096, gat_br+3*64, gat_attn+3*64, B.sie);

    // 6. user_item_embed = mlp0([iie, sie])
    run_mlp(B, B.rc, B.sie, mlp_W+0*8192, mlp_b+0*64, mlp_g+0*64, mlp_beta+0*64,
            B.uitem, NPREDN, B.stat + 128);

    // 7. Cheb layer 1 (T0 = ebn[:TOTAL]); second lhat emits T2 = 2*lhat(T1)-T0
    k_lhat_node<<<ceil_div(NTOTN*16,256),256>>>(rp_snn, sc_snn, B.normv, B.ebn, lam,
                                                nullptr, B.T1, NTOTN);
    k_lhat_node<<<ceil_div(NTOTN*16,256),256>>>(rp_snn, sc_snn, B.normv, B.T1, lam,
                                                B.ebn, B.T2, NTOTN);
    k_gemm_cat3<<<ceil_div(NTOTN,64),128>>>(B.ebn, B.T1, B.T2, cheb_W, cheb_b, B.ch, NTOTN);

    // 8. Cheb layer 2
    k_lhat_node<<<ceil_div(NTOTN*16,256),256>>>(rp_snn, sc_snn, B.normv, B.ch, lam,
                                                nullptr, B.T1, NTOTN);
    k_lhat_node<<<ceil_div(NTOTN*16,256),256>>>(rp_snn, sc_snn, B.normv, B.T1, lam,
                                                B.ch, B.T2, NTOTN);
    k_gemm_cat3<<<ceil_div(NTOTN,64),128>>>(B.ch, B.T1, B.T2, cheb_W, cheb_b, B.ch2, NTOTN);

    // 9. GAT4 (snn)
    run_gat(B, rp_snn, sc_snn, B.ch2, nullptr, NTOTN,
            gat_Wl+4*4096, gat_bl+4*64, gat_Wr+4*4096, gat_br+4*64, gat_attn+4*64, B.gout);

    // 10. h_uP, h_uS
    run_mlp(B, B.uitem, B.ebn, mlp_W+1*8192, mlp_b+1*64, mlp_g+1*64, mlp_beta+1*64,
            B.huP, NPREDN, B.stat + 2*128);
    run_mlp(B, B.gout,  B.ebn, mlp_W+2*8192, mlp_b+2*64, mlp_g+2*64, mlp_beta+2*64,
            B.huS, NPREDN, B.stat + 3*128);

    // 11. fused gating + final MLPs
    k_softmul2<<<ceil_div(NPREDN*16,256),256>>>(B.huP, B.huS, B.mA, B.mA2, NPREDN);
    run_mlp(B, B.mA, B.huP, mlp_W+3*8192, mlp_b+3*64, mlp_g+3*64, mlp_beta+3*64,
            out, NPREDN, B.stat + 4*128);
    run_mlp(B, B.mA2, B.huS, mlp_W+4*8192, mlp_b+4*64, mlp_g+4*64, mlp_beta+4*64,
            out + (size_t)NPREDN*EMBD, NPREDN, B.stat + 5*128);
}